// round 8
// baseline (speedup 1.0000x reference)
#include <cuda_runtime.h>
#include <cuda_bf16.h>
#include <math.h>

#define BB 16
#define TT 4096
#define DD 512
#define CCH 10
#define FWD 100
#define KW 201          // 2*FW+1
#define NBLK 4          // N split: 4 tiles of 128 columns

// ---------------- device scratch (static, allowed) ----------------
__device__ __align__(16) __nv_bfloat16 g_Whi[DD * DD];
__device__ __align__(16) __nv_bfloat16 g_Wlo[DD * DD];
__device__ __align__(16) __nv_bfloat16 g_Vhi[(size_t)BB * TT * DD];
__device__ __align__(16) __nv_bfloat16 g_Vlo[(size_t)BB * TT * DD];
__device__ float g_dec[BB * DD];                 // dec projection + b_enc
__device__ float g_conv[BB * TT * CCH];          // conv features [b][t][c]
__device__ float g_epart[NBLK * BB * TT];        // partial logits per N-block
__device__ float g_ctxpart[8 * BB * DD];         // context partials per T-chunk

// ---------------- helpers ----------------
__device__ __forceinline__ unsigned pack_bf2(float x, float y) {
    __nv_bfloat162 h = __floats2bfloat162_rn(x, y);
    return *reinterpret_cast<unsigned*>(&h);
}
__device__ __forceinline__ float tanh_fast(float x) {
    float ax = fabsf(x);
    float z = __expf(-2.0f * ax);
    float t = __fdividef(1.0f - z, 1.0f + z);
    return copysignf(t, x);
}

// pure register op: NOT volatile, lets ptxas interleave freely
__device__ __forceinline__ void mma_bf16(float* d, const unsigned* a,
                                         unsigned b0, unsigned b1) {
    asm("mma.sync.aligned.m16n8k16.row.col.f32.bf16.bf16.f32 "
        "{%0,%1,%2,%3}, {%4,%5,%6,%7}, {%8,%9}, {%0,%1,%2,%3};\n"
        : "+f"(d[0]), "+f"(d[1]), "+f"(d[2]), "+f"(d[3])
        : "r"(a[0]), "r"(a[1]), "r"(a[2]), "r"(a[3]), "r"(b0), "r"(b1));
}

__device__ __forceinline__ void ldsm4(unsigned* r, unsigned addr) {
    asm volatile("ldmatrix.sync.aligned.m8n8.x4.shared.b16 {%0,%1,%2,%3}, [%4];\n"
                 : "=r"(r[0]), "=r"(r[1]), "=r"(r[2]), "=r"(r[3]) : "r"(addr));
}

#define CP_ASYNC16(sm, gm) \
    asm volatile("cp.async.cg.shared.global [%0], [%1], 16;\n" :: "r"(sm), "l"(gm))
#define CP_COMMIT() asm volatile("cp.async.commit_group;\n")
#define CP_WAIT(n)  asm volatile("cp.async.wait_group %0;\n" :: "n"(n))

// ---------------- kernel 1: split W_enc into bf16 hi/lo ----------------
__global__ void k_split(const float* __restrict__ W) {
    int i = blockIdx.x * blockDim.x + threadIdx.x;
    float w = W[i];
    __nv_bfloat16 hi = __float2bfloat16(w);
    g_Whi[i] = hi;
    g_Wlo[i] = __float2bfloat16(w - __bfloat162float(hi));
}

// ---------------- kernel 1b: split value into bf16 hi/lo ----------------
__global__ void __launch_bounds__(256) k_vsplit(const float* __restrict__ v) {
    size_t i = ((size_t)blockIdx.x * 256 + threadIdx.x) * 4;
    float4 x = *(const float4*)(v + i);
    __nv_bfloat16 h0 = __float2bfloat16(x.x);
    __nv_bfloat16 h1 = __float2bfloat16(x.y);
    __nv_bfloat16 h2 = __float2bfloat16(x.z);
    __nv_bfloat16 h3 = __float2bfloat16(x.w);
    __nv_bfloat162 ph0; ph0.x = h0; ph0.y = h1;
    __nv_bfloat162 ph1; ph1.x = h2; ph1.y = h3;
    uint2 hv = make_uint2(*(unsigned*)&ph0, *(unsigned*)&ph1);
    uint2 lv = make_uint2(pack_bf2(x.x - __bfloat162float(h0),
                                   x.y - __bfloat162float(h1)),
                          pack_bf2(x.z - __bfloat162float(h2),
                                   x.w - __bfloat162float(h3)));
    *reinterpret_cast<uint2*>(g_Vhi + i) = hv;
    *reinterpret_cast<uint2*>(g_Vlo + i) = lv;
}

// ---------------- kernel 2: dec projection + b_enc ----------------
__global__ void k_dec(const float* __restrict__ query,
                      const float* __restrict__ Wdec,
                      const float* __restrict__ b_enc) {
    __shared__ float q[DD];
    int b = blockIdx.x;
    int e = threadIdx.x;
    q[e] = query[b * DD + e];
    __syncthreads();
    float acc = b_enc[e];
    const float* wr = Wdec + e * DD;
#pragma unroll 8
    for (int d = 0; d < DD; ++d) acc += q[d] * wr[d];
    g_dec[b * DD + e] = acc;
}

// ---------------- kernel 3: location conv (att_prev -> [b][t][10]) ------
__global__ void k_conv(const float* __restrict__ att_prev,
                       const float* __restrict__ Wconv) {
    __shared__ float win[256 + 2 * FWD];
    __shared__ float wc[CCH * KW];
    int t0 = blockIdx.x * 256;
    int b = blockIdx.y;
    int tid = threadIdx.x;                 // 256
    for (int i = tid; i < 256 + 2 * FWD; i += 256) {
        int gidx = t0 - FWD + i;
        win[i] = (gidx >= 0 && gidx < TT) ? att_prev[b * TT + gidx] : 0.f;
    }
    for (int i = tid; i < CCH * KW; i += 256) wc[i] = Wconv[i];
    __syncthreads();
    float acc[CCH];
#pragma unroll
    for (int c = 0; c < CCH; ++c) acc[c] = 0.f;
    for (int h = 0; h < KW; ++h) {
        float x = win[tid + h];
#pragma unroll
        for (int c = 0; c < CCH; ++c) acc[c] += x * wc[c * KW + h];
    }
    float* o = &g_conv[(size_t)(b * TT + t0 + tid) * CCH];
#pragma unroll
    for (int c = 0; c < CCH; ++c) o[c] = acc[c];
}

// ---------------- kernel 4: fused split-bf16 GEMM + epilogue -> logits --
// 128(t) x 128(e) tile, KC=32, 4-stage cp.async pipeline, 1 barrier/iter,
// 512 threads / 16 warps (4m x 4n, warp tile 32x32) -> 4 warps/SMSP.
// Term-major MMA issue. Grid: x = N-block (A-tile L2 reuse).
#define KC 32
#define NCHUNK (DD / KC)       // 16
#define NSTAGE 4
#define ROWU 20                // padded row stride in uints (80 B)
#define ARR_BYTES (128u * ROWU * 4u)      // 10240 B per array
#define STAGE_BYTES (4u * ARR_BYTES)      // 40960 B: Ahi|Alo|Bhi|Blo
#define GEMM_SMEM (NSTAGE * STAGE_BYTES)  // 163840 B

__global__ void __launch_bounds__(512, 1)
k_gemm(const float* __restrict__ Watt,
       const float* __restrict__ wg) {
    extern __shared__ __align__(16) char dsm[];
    int tid = threadIdx.x;
    int b = blockIdx.z;
    int e0 = blockIdx.x * 128;             // N-block fastest -> A L2 reuse
    int t0 = blockIdx.y * 128;
    int lane = tid & 31, warp = tid >> 5;
    int wm = warp & 3, wn = warp >> 2;     // 4m x 4n warps, 32x32 warp tile
    int g = lane >> 2, c = lane & 3;

    float acc[2][4][4];
#pragma unroll
    for (int mt = 0; mt < 2; ++mt)
#pragma unroll
        for (int nt = 0; nt < 4; ++nt)
#pragma unroll
            for (int q = 0; q < 4; ++q) acc[mt][nt][q] = 0.f;

    unsigned sbase = (unsigned)__cvta_generic_to_shared(dsm);

    // cp.async mapping: thread -> (array = tid>>7, row = tid&127), 4 segs
    int car = tid >> 7, crow = tid & 127;
    const __nv_bfloat16* gsrc;
    if (car == 0)
        gsrc = g_Vhi + ((size_t)(b * TT + t0 + crow)) * DD;
    else if (car == 1)
        gsrc = g_Vlo + ((size_t)(b * TT + t0 + crow)) * DD;
    else if (car == 2)
        gsrc = g_Whi + (size_t)(e0 + crow) * DD;
    else
        gsrc = g_Wlo + (size_t)(e0 + crow) * DD;
    unsigned sdst = (unsigned)car * ARR_BYTES + (unsigned)(crow * ROWU * 4);

#define ISSUE_STAGE(s, k0)                                                    \
    do {                                                                      \
        unsigned sb = sbase + (unsigned)(s) * STAGE_BYTES + sdst;             \
        const __nv_bfloat16* gp = gsrc + (k0);                                \
        CP_ASYNC16(sb,      gp);                                              \
        CP_ASYNC16(sb + 16, gp + 8);                                          \
        CP_ASYNC16(sb + 32, gp + 16);                                         \
        CP_ASYNC16(sb + 48, gp + 24);                                         \
    } while (0)

    int lr = ((lane >> 3) & 1) * 8 + (lane & 7);
    int lc = ((lane >> 4) & 1) * 4;

    ISSUE_STAGE(0, 0); CP_COMMIT();
    ISSUE_STAGE(1, KC); CP_COMMIT();
    ISSUE_STAGE(2, 2 * KC); CP_COMMIT();

    for (int it = 0; it < NCHUNK; ++it) {
        CP_WAIT(2);
        __syncthreads();
        unsigned stb = sbase + (unsigned)(it & 3) * STAGE_BYTES;

#pragma unroll
        for (int ks = 0; ks < 2; ++ks) {
            unsigned kso = (unsigned)(ks * 32);    // 8 uints = 32 bytes
            unsigned ahi[2][4], alo[2][4], bh[2][4], bl[2][4];
#pragma unroll
            for (int mt = 0; mt < 2; ++mt) {
                unsigned ao = stb +
                    (unsigned)((wm * 32 + mt * 16 + lr) * ROWU * 4 + lc * 4) + kso;
                ldsm4(ahi[mt], ao);
                ldsm4(alo[mt], ao + ARR_BYTES);
            }
#pragma unroll
            for (int ntp = 0; ntp < 2; ++ntp) {
                unsigned bo = stb + 2 * ARR_BYTES +
                    (unsigned)((wn * 32 + ntp * 16 + lr) * ROWU * 4 + lc * 4) + kso;
                ldsm4(bh[ntp], bo);
                ldsm4(bl[ntp], bo + ARR_BYTES);
            }
            // term-major issue: consecutive MMAs hit different accumulators
#pragma unroll
            for (int ntp = 0; ntp < 2; ++ntp)
#pragma unroll
                for (int sub = 0; sub < 2; ++sub)
#pragma unroll
                    for (int mt = 0; mt < 2; ++mt)
                        mma_bf16(acc[mt][ntp * 2 + sub], ahi[mt],
                                 bh[ntp][sub], bh[ntp][2 + sub]);
#pragma unroll
            for (int ntp = 0; ntp < 2; ++ntp)
#pragma unroll
                for (int sub = 0; sub < 2; ++sub)
#pragma unroll
                    for (int mt = 0; mt < 2; ++mt)
                        mma_bf16(acc[mt][ntp * 2 + sub], ahi[mt],
                                 bl[ntp][sub], bl[ntp][2 + sub]);
#pragma unroll
            for (int ntp = 0; ntp < 2; ++ntp)
#pragma unroll
                for (int sub = 0; sub < 2; ++sub)
#pragma unroll
                    for (int mt = 0; mt < 2; ++mt)
                        mma_bf16(acc[mt][ntp * 2 + sub], alo[mt],
                                 bh[ntp][sub], bh[ntp][2 + sub]);
        }
        if (it + 3 < NCHUNK) ISSUE_STAGE((it + 3) & 3, (it + 3) * KC);
        CP_COMMIT();
    }
    __syncthreads();   // all stages consumed; safe to overlay epilogue

    // ---- epilogue smem overlay on dynamic smem ----
    float* econv = (float*)dsm;              // [128][10]
    float* ewatt = econv + 1280;             // [128][10]
    float* edec  = ewatt + 1280;             // [128]
    float* ewg   = edec + 128;               // [128]
    float* ered  = ewg + 128;                // [128][4]

    for (int i = tid; i < 1280; i += 512) {
        int row = i / 10, cc = i - row * 10;
        econv[i] = g_conv[(size_t)(b * TT + t0 + row) * CCH + cc];
        ewatt[i] = Watt[(e0 + row) * CCH + cc];
    }
    if (tid < 128) {
        edec[tid] = g_dec[b * DD + e0 + tid];
        ewg[tid] = wg[e0 + tid];
    }
    __syncthreads();

    float rowsum[2][2];
#pragma unroll
    for (int mt = 0; mt < 2; ++mt)
#pragma unroll
        for (int rr = 0; rr < 2; ++rr) {
            int rowl = wm * 32 + mt * 16 + rr * 8 + g;
            float sacc = 0.f;
#pragma unroll
            for (int nt = 0; nt < 4; ++nt)
#pragma unroll
                for (int q = 0; q < 2; ++q) {
                    int el = wn * 32 + nt * 8 + 2 * c + q;
                    float v = acc[mt][nt][rr * 2 + q] + edec[el];
#pragma unroll
                    for (int cc = 0; cc < CCH; ++cc)
                        v += econv[rowl * 10 + cc] * ewatt[el * 10 + cc];
                    sacc += ewg[el] * tanh_fast(v);
                }
            rowsum[mt][rr] = sacc;
        }
#pragma unroll
    for (int mt = 0; mt < 2; ++mt)
#pragma unroll
        for (int rr = 0; rr < 2; ++rr) {
            float v = rowsum[mt][rr];
            v += __shfl_xor_sync(0xffffffffu, v, 1);
            v += __shfl_xor_sync(0xffffffffu, v, 2);
            rowsum[mt][rr] = v;
        }
    if (c == 0) {
#pragma unroll
        for (int mt = 0; mt < 2; ++mt)
#pragma unroll
            for (int rr = 0; rr < 2; ++rr)
                ered[(wm * 32 + mt * 16 + rr * 8 + g) * 4 + wn] = rowsum[mt][rr];
    }
    __syncthreads();
    if (tid < 128) {
        float val = ered[tid * 4] + ered[tid * 4 + 1] +
                    ered[tid * 4 + 2] + ered[tid * 4 + 3];
        g_epart[((size_t)blockIdx.x * BB + b) * TT + t0 + tid] = val;
    }
}

// ---------------- kernel 5: masked sharpened softmax ----------------
__global__ void k_softmax(const int* __restrict__ lens,
                          float* __restrict__ out_att) {
    int b = blockIdx.x;
    int tid = threadIdx.x;            // 256
    int len = lens[b];
    __shared__ float sred[256];
    float ev[16];
    float lmax = -INFINITY;
#pragma unroll
    for (int i = 0; i < 16; ++i) {
        int t = tid + i * 256;
        float e = g_epart[(0 * BB + b) * TT + t] +
                  g_epart[(1 * BB + b) * TT + t] +
                  g_epart[(2 * BB + b) * TT + t] +
                  g_epart[(3 * BB + b) * TT + t];
        e *= 2.0f;                    // sharpening
        ev[i] = (t < len) ? e : -INFINITY;
        lmax = fmaxf(lmax, ev[i]);
    }
    sred[tid] = lmax;
    __syncthreads();
    for (int s = 128; s > 0; s >>= 1) {
        if (tid < s) sred[tid] = fmaxf(sred[tid], sred[tid + s]);
        __syncthreads();
    }
    float m = sred[0];
    __syncthreads();
    float lsum = 0.f;
#pragma unroll
    for (int i = 0; i < 16; ++i) {
        float p = expf(ev[i] - m);
        ev[i] = p;
        lsum += p;
    }
    sred[tid] = lsum;
    __syncthreads();
    for (int s = 128; s > 0; s >>= 1) {
        if (tid < s) sred[tid] += sred[tid + s];
        __syncthreads();
    }
    float inv = 1.f / sred[0];
#pragma unroll
    for (int i = 0; i < 16; ++i)
        out_att[b * TT + tid + i * 256] = ev[i] * inv;
}

// ---------------- kernel 6/7: context = value^T @ weights ----------------
__global__ void k_ctx_part(const float* __restrict__ value,
                           const float* __restrict__ att) {
    int dch = blockIdx.x, tch = blockIdx.y, b = blockIdx.z;
    int dl = threadIdx.x & 127;
    int tl = threadIdx.x >> 7;
    int d = dch * 128 + dl;
    const float* vb = value + (size_t)b * TT * DD;
    const float* ab = att + b * TT;
    float acc = 0.f;
    int tbase = tch * 512;
    for (int t = tbase + tl; t < tbase + 512; t += 2)
        acc += vb[(size_t)t * DD + d] * ab[t];
    __shared__ float s[256];
    s[threadIdx.x] = acc;
    __syncthreads();
    if (tl == 0)
        g_ctxpart[((size_t)tch * BB + b) * DD + d] = s[dl] + s[dl + 128];
}

__global__ void k_ctx_final(float* __restrict__ out) {
    int idx = blockIdx.x * 256 + threadIdx.x;
    float v = 0.f;
#pragma unroll
    for (int p = 0; p < 8; ++p) v += g_ctxpart[p * BB * DD + idx];
    out[idx] = v;
}

// ---------------- launch ----------------
extern "C" void kernel_launch(void* const* d_in, const int* in_sizes, int n_in,
                              void* d_out, int out_size) {
    const float* value    = (const float*)d_in[0];
    const float* query    = (const float*)d_in[1];
    const int*   lens     = (const int*)d_in[2];
    const float* att_prev = (const float*)d_in[3];
    const float* W_enc    = (const float*)d_in[4];
    const float* b_enc    = (const float*)d_in[5];
    const float* W_dec    = (const float*)d_in[6];
    const float* W_att    = (const float*)d_in[7];
    const float* W_conv   = (const float*)d_in[8];
    const float* w_g      = (const float*)d_in[9];
    // d_in[10] = b_g: uniform logit shift, cancels in softmax.

    float* out = (float*)d_out;
    float* out_att = out + BB * DD;

    cudaFuncSetAttribute(k_gemm, cudaFuncAttributeMaxDynamicSharedMemorySize,
                         GEMM_SMEM);

    k_split<<<512, 512>>>(W_enc);
    k_vsplit<<<(BB * TT * DD) / (4 * 256), 256>>>(value);
    k_dec<<<BB, DD>>>(query, W_dec, b_enc);
    k_conv<<<dim3(TT / 256, BB), 256>>>(att_prev, W_conv);
    k_gemm<<<dim3(NBLK, TT / 128, BB), 512, GEMM_SMEM>>>(W_att, w_g);
    k_softmax<<<BB, 256>>>(lens, out_att);
    k_ctx_part<<<dim3(4, 8, BB), 256>>>(value, out_att);
    k_ctx_final<<<BB * DD / 256, 256>>>(out);
}

// round 9
// speedup vs baseline: 1.1079x; 1.1079x over previous
#include <cuda_runtime.h>
#include <cuda_fp16.h>
#include <math.h>

#define BB 16
#define TT 4096
#define DD 512
#define CCH 10
#define FWD 100
#define KW 201          // 2*FW+1
#define NBLK 4          // N split: 4 tiles of 128 columns

// ---------------- device scratch (static, allowed) ----------------
__device__ __align__(16) __half g_Wh[DD * DD];                  // W_enc fp16
__device__ __align__(16) __half g_Vh[(size_t)BB * TT * DD];     // value hi
__device__ __align__(16) __half g_Vl[(size_t)BB * TT * DD];     // value lo
__device__ float g_dec[BB * DD];                 // dec projection + b_enc
__device__ float g_conv[BB * TT * CCH];          // conv features [b][t][c]
__device__ float g_epart[NBLK * BB * TT];        // partial logits per N-block
__device__ float g_ctxpart[8 * BB * DD];         // context partials per T-chunk

// ---------------- helpers ----------------
__device__ __forceinline__ float tanh_fast(float x) {
    float ax = fabsf(x);
    float z = __expf(-2.0f * ax);
    float t = __fdividef(1.0f - z, 1.0f + z);
    return copysignf(t, x);
}

// fp16 MMA, fp32 accum. NOT volatile: ptxas may interleave freely.
__device__ __forceinline__ void mma_f16(float* d, const unsigned* a,
                                        unsigned b0, unsigned b1) {
    asm("mma.sync.aligned.m16n8k16.row.col.f32.f16.f16.f32 "
        "{%0,%1,%2,%3}, {%4,%5,%6,%7}, {%8,%9}, {%0,%1,%2,%3};\n"
        : "+f"(d[0]), "+f"(d[1]), "+f"(d[2]), "+f"(d[3])
        : "r"(a[0]), "r"(a[1]), "r"(a[2]), "r"(a[3]), "r"(b0), "r"(b1));
}

__device__ __forceinline__ void ldsm4(unsigned* r, unsigned addr) {
    asm volatile("ldmatrix.sync.aligned.m8n8.x4.shared.b16 {%0,%1,%2,%3}, [%4];\n"
                 : "=r"(r[0]), "=r"(r[1]), "=r"(r[2]), "=r"(r[3]) : "r"(addr));
}

#define CP_ASYNC16(sm, gm) \
    asm volatile("cp.async.cg.shared.global [%0], [%1], 16;\n" :: "r"(sm), "l"(gm))
#define CP_COMMIT() asm volatile("cp.async.commit_group;\n")
#define CP_WAIT(n)  asm volatile("cp.async.wait_group %0;\n" :: "n"(n))

// ---------------- kernel 1: W_enc -> fp16 ----------------
__global__ void k_split(const float* __restrict__ W) {
    int i = blockIdx.x * blockDim.x + threadIdx.x;
    g_Wh[i] = __float2half_rn(W[i]);
}

// ---------------- kernel 1b: value -> fp16 hi/lo ----------------
__global__ void __launch_bounds__(256) k_vsplit(const float* __restrict__ v) {
    size_t i = ((size_t)blockIdx.x * 256 + threadIdx.x) * 4;
    float4 x = *(const float4*)(v + i);
    __half h0 = __float2half_rn(x.x);
    __half h1 = __float2half_rn(x.y);
    __half h2 = __float2half_rn(x.z);
    __half h3 = __float2half_rn(x.w);
    __half2 ph0 = __halves2half2(h0, h1);
    __half2 ph1 = __halves2half2(h2, h3);
    __half2 pl0 = __floats2half2_rn(x.x - __half2float(h0),
                                    x.y - __half2float(h1));
    __half2 pl1 = __floats2half2_rn(x.z - __half2float(h2),
                                    x.w - __half2float(h3));
    uint2 hv = make_uint2(*(unsigned*)&ph0, *(unsigned*)&ph1);
    uint2 lv = make_uint2(*(unsigned*)&pl0, *(unsigned*)&pl1);
    *reinterpret_cast<uint2*>(g_Vh + i) = hv;
    *reinterpret_cast<uint2*>(g_Vl + i) = lv;
}

// ---------------- kernel 2: dec projection + b_enc ----------------
__global__ void k_dec(const float* __restrict__ query,
                      const float* __restrict__ Wdec,
                      const float* __restrict__ b_enc) {
    __shared__ float q[DD];
    int b = blockIdx.x;
    int e = threadIdx.x;
    q[e] = query[b * DD + e];
    __syncthreads();
    float acc = b_enc[e];
    const float* wr = Wdec + e * DD;
#pragma unroll 8
    for (int d = 0; d < DD; ++d) acc += q[d] * wr[d];
    g_dec[b * DD + e] = acc;
}

// ---------------- kernel 3: location conv (att_prev -> [b][t][10]) ------
__global__ void k_conv(const float* __restrict__ att_prev,
                       const float* __restrict__ Wconv) {
    __shared__ float win[256 + 2 * FWD];
    __shared__ float wc[CCH * KW];
    int t0 = blockIdx.x * 256;
    int b = blockIdx.y;
    int tid = threadIdx.x;                 // 256
    for (int i = tid; i < 256 + 2 * FWD; i += 256) {
        int gidx = t0 - FWD + i;
        win[i] = (gidx >= 0 && gidx < TT) ? att_prev[b * TT + gidx] : 0.f;
    }
    for (int i = tid; i < CCH * KW; i += 256) wc[i] = Wconv[i];
    __syncthreads();
    float acc[CCH];
#pragma unroll
    for (int c = 0; c < CCH; ++c) acc[c] = 0.f;
    for (int h = 0; h < KW; ++h) {
        float x = win[tid + h];
#pragma unroll
        for (int c = 0; c < CCH; ++c) acc[c] += x * wc[c * KW + h];
    }
    float* o = &g_conv[(size_t)(b * TT + t0 + tid) * CCH];
#pragma unroll
    for (int c = 0; c < CCH; ++c) o[c] = acc[c];
}

// ---------------- kernel 4: fused 2-term fp16 GEMM + epilogue -----------
// 128(t) x 128(e) tile, KC=32, 4-stage cp.async, 1 barrier/iter,
// 256 threads (8 warps, 4m x 2n). Terms: Vhi*Wh + Vlo*Wh (2 MMAs/tile/ks).
#define KC 32
#define NCHUNK (DD / KC)       // 16
#define NSTAGE 4
#define ROWU 20                // padded row stride in uints (80 B)
#define ARR_BYTES (128u * ROWU * 4u)      // 10240 B per array
#define STAGE_BYTES (3u * ARR_BYTES)      // 30720 B: Ahi|Alo|B
#define GEMM_SMEM (NSTAGE * STAGE_BYTES)  // 122880 B

__global__ void __launch_bounds__(256)
k_gemm(const float* __restrict__ Watt,
       const float* __restrict__ wg) {
    extern __shared__ __align__(16) char dsm[];
    int tid = threadIdx.x;
    int b = blockIdx.z;
    int e0 = blockIdx.x * 128;             // N-block fastest -> A L2 reuse
    int t0 = blockIdx.y * 128;
    int lane = tid & 31, warp = tid >> 5;
    int wm = warp & 3, wn = warp >> 2;     // 4m x 2n warps
    int g = lane >> 2, c = lane & 3;

    float acc[2][8][4];
#pragma unroll
    for (int mt = 0; mt < 2; ++mt)
#pragma unroll
        for (int nt = 0; nt < 8; ++nt)
#pragma unroll
            for (int q = 0; q < 4; ++q) acc[mt][nt][q] = 0.f;

    unsigned sbase = (unsigned)__cvta_generic_to_shared(dsm);

    // cp.async mapping: thread -> row = tid>>1, seg pair = (tid&1)*2
    int row0 = tid >> 1, hseg = (tid & 1) * 2;   // segs {0,1} or {2,3}
    unsigned soff = (unsigned)(row0 * ROWU * 4 + hseg * 16);
    const __half* gAh = g_Vh + ((size_t)(b * TT + t0 + row0)) * DD + hseg * 8;
    const __half* gAl = g_Vl + ((size_t)(b * TT + t0 + row0)) * DD + hseg * 8;
    const __half* gB  = g_Wh + (size_t)(e0 + row0) * DD + hseg * 8;

#define ISSUE_STAGE(s, k0)                                                    \
    do {                                                                      \
        unsigned sb = sbase + (unsigned)(s) * STAGE_BYTES + soff;             \
        CP_ASYNC16(sb, gAh + (k0));                                           \
        CP_ASYNC16(sb + 16, gAh + (k0) + 8);                                  \
        CP_ASYNC16(sb + ARR_BYTES, gAl + (k0));                               \
        CP_ASYNC16(sb + ARR_BYTES + 16, gAl + (k0) + 8);                      \
        CP_ASYNC16(sb + 2 * ARR_BYTES, gB + (k0));                            \
        CP_ASYNC16(sb + 2 * ARR_BYTES + 16, gB + (k0) + 8);                   \
    } while (0)

    int lr = ((lane >> 3) & 1) * 8 + (lane & 7);
    int lc = ((lane >> 4) & 1) * 4;

    ISSUE_STAGE(0, 0); CP_COMMIT();
    ISSUE_STAGE(1, KC); CP_COMMIT();
    ISSUE_STAGE(2, 2 * KC); CP_COMMIT();

    for (int it = 0; it < NCHUNK; ++it) {
        CP_WAIT(2);
        __syncthreads();
        unsigned stb = sbase + (unsigned)(it & 3) * STAGE_BYTES;

#pragma unroll
        for (int ks = 0; ks < 2; ++ks) {
            unsigned kso = (unsigned)(ks * 32);    // 8 uints = 32 bytes
            unsigned ahi[2][4], alo[2][4], bf[4][4];
#pragma unroll
            for (int mt = 0; mt < 2; ++mt) {
                unsigned ao = stb +
                    (unsigned)((wm * 32 + mt * 16 + lr) * ROWU * 4 + lc * 4) + kso;
                ldsm4(ahi[mt], ao);
                ldsm4(alo[mt], ao + ARR_BYTES);
            }
#pragma unroll
            for (int ntp = 0; ntp < 4; ++ntp) {
                unsigned bo = stb + 2 * ARR_BYTES +
                    (unsigned)((wn * 64 + ntp * 16 + lr) * ROWU * 4 + lc * 4) + kso;
                ldsm4(bf[ntp], bo);
            }
            // term-major issue: consecutive MMAs hit different accumulators
#pragma unroll
            for (int ntp = 0; ntp < 4; ++ntp)
#pragma unroll
                for (int sub = 0; sub < 2; ++sub)
#pragma unroll
                    for (int mt = 0; mt < 2; ++mt)
                        mma_f16(acc[mt][ntp * 2 + sub], ahi[mt],
                                bf[ntp][sub], bf[ntp][2 + sub]);
#pragma unroll
            for (int ntp = 0; ntp < 4; ++ntp)
#pragma unroll
                for (int sub = 0; sub < 2; ++sub)
#pragma unroll
                    for (int mt = 0; mt < 2; ++mt)
                        mma_f16(acc[mt][ntp * 2 + sub], alo[mt],
                                bf[ntp][sub], bf[ntp][2 + sub]);
        }
        if (it + 3 < NCHUNK) ISSUE_STAGE((it + 3) & 3, (it + 3) * KC);
        CP_COMMIT();
    }
    __syncthreads();   // all stages consumed; safe to overlay epilogue

    // ---- epilogue smem overlay on dynamic smem ----
    float* econv = (float*)dsm;              // [128][10]
    float* ewatt = econv + 1280;             // [128][10]
    float* edec  = ewatt + 1280;             // [128]
    float* ewg   = edec + 128;               // [128]
    float* ered  = ewg + 128;                // [128][2]

    for (int i = tid; i < 1280; i += 256) {
        int row = i / 10, cc = i - row * 10;
        econv[i] = g_conv[(size_t)(b * TT + t0 + row) * CCH + cc];
        ewatt[i] = Watt[(e0 + row) * CCH + cc];
    }
    if (tid < 128) {
        edec[tid] = g_dec[b * DD + e0 + tid];
        ewg[tid] = wg[e0 + tid];
    }
    __syncthreads();

    float rowsum[2][2];
#pragma unroll
    for (int mt = 0; mt < 2; ++mt)
#pragma unroll
        for (int rr = 0; rr < 2; ++rr) {
            int rowl = wm * 32 + mt * 16 + rr * 8 + g;
            float sacc = 0.f;
#pragma unroll
            for (int nt = 0; nt < 8; ++nt)
#pragma unroll
                for (int q = 0; q < 2; ++q) {
                    int el = wn * 64 + nt * 8 + 2 * c + q;
                    float v = acc[mt][nt][rr * 2 + q] + edec[el];
#pragma unroll
                    for (int cc = 0; cc < CCH; ++cc)
                        v += econv[rowl * 10 + cc] * ewatt[el * 10 + cc];
                    sacc += ewg[el] * tanh_fast(v);
                }
            rowsum[mt][rr] = sacc;
        }
#pragma unroll
    for (int mt = 0; mt < 2; ++mt)
#pragma unroll
        for (int rr = 0; rr < 2; ++rr) {
            float v = rowsum[mt][rr];
            v += __shfl_xor_sync(0xffffffffu, v, 1);
            v += __shfl_xor_sync(0xffffffffu, v, 2);
            rowsum[mt][rr] = v;
        }
    if (c == 0) {
#pragma unroll
        for (int mt = 0; mt < 2; ++mt)
#pragma unroll
            for (int rr = 0; rr < 2; ++rr)
                ered[(wm * 32 + mt * 16 + rr * 8 + g) * 2 + wn] = rowsum[mt][rr];
    }
    __syncthreads();
    if (tid < 128) {
        float val = ered[tid * 2] + ered[tid * 2 + 1];
        g_epart[((size_t)blockIdx.x * BB + b) * TT + t0 + tid] = val;
    }
}

// ---------------- kernel 5: masked sharpened softmax ----------------
__global__ void k_softmax(const int* __restrict__ lens,
                          float* __restrict__ out_att) {
    int b = blockIdx.x;
    int tid = threadIdx.x;            // 256
    int len = lens[b];
    __shared__ float sred[256];
    float ev[16];
    float lmax = -INFINITY;
#pragma unroll
    for (int i = 0; i < 16; ++i) {
        int t = tid + i * 256;
        float e = g_epart[(0 * BB + b) * TT + t] +
                  g_epart[(1 * BB + b) * TT + t] +
                  g_epart[(2 * BB + b) * TT + t] +
                  g_epart[(3 * BB + b) * TT + t];
        e *= 2.0f;                    // sharpening
        ev[i] = (t < len) ? e : -INFINITY;
        lmax = fmaxf(lmax, ev[i]);
    }
    sred[tid] = lmax;
    __syncthreads();
    for (int s = 128; s > 0; s >>= 1) {
        if (tid < s) sred[tid] = fmaxf(sred[tid], sred[tid + s]);
        __syncthreads();
    }
    float m = sred[0];
    __syncthreads();
    float lsum = 0.f;
#pragma unroll
    for (int i = 0; i < 16; ++i) {
        float p = expf(ev[i] - m);
        ev[i] = p;
        lsum += p;
    }
    sred[tid] = lsum;
    __syncthreads();
    for (int s = 128; s > 0; s >>= 1) {
        if (tid < s) sred[tid] += sred[tid + s];
        __syncthreads();
    }
    float inv = 1.f / sred[0];
#pragma unroll
    for (int i = 0; i < 16; ++i)
        out_att[b * TT + tid + i * 256] = ev[i] * inv;
}

// ---------------- kernel 6/7: context = value^T @ weights ----------------
__global__ void __launch_bounds__(128) k_ctx_part(const float* __restrict__ value,
                                                  const float* __restrict__ att) {
    int tch = blockIdx.x, b = blockIdx.y;
    int d4 = threadIdx.x * 4;
    const float* vb = value + (size_t)b * TT * DD;
    const float* ab = att + b * TT;
    float a0 = 0.f, a1 = 0.f, a2 = 0.f, a3 = 0.f;
    int tbase = tch * 512;
#pragma unroll 4
    for (int t = tbase; t < tbase + 512; ++t) {
        float4 v = *(const float4*)(vb + (size_t)t * DD + d4);
        float w = __ldg(ab + t);
        a0 += v.x * w; a1 += v.y * w; a2 += v.z * w; a3 += v.w * w;
    }
    float* o = &g_ctxpart[((size_t)tch * BB + b) * DD + d4];
    o[0] = a0; o[1] = a1; o[2] = a2; o[3] = a3;
}

__global__ void k_ctx_final(float* __restrict__ out) {
    int idx = blockIdx.x * 256 + threadIdx.x;
    float v = 0.f;
#pragma unroll
    for (int p = 0; p < 8; ++p) v += g_ctxpart[p * BB * DD + idx];
    out[idx] = v;
}

// ---------------- launch ----------------
extern "C" void kernel_launch(void* const* d_in, const int* in_sizes, int n_in,
                              void* d_out, int out_size) {
    const float* value    = (const float*)d_in[0];
    const float* query    = (const float*)d_in[1];
    const int*   lens     = (const int*)d_in[2];
    const float* att_prev = (const float*)d_in[3];
    const float* W_enc    = (const float*)d_in[4];
    const float* b_enc    = (const float*)d_in[5];
    const float* W_dec    = (const float*)d_in[6];
    const float* W_att    = (const float*)d_in[7];
    const float* W_conv   = (const float*)d_in[8];
    const float* w_g      = (const float*)d_in[9];
    // d_in[10] = b_g: uniform logit shift, cancels in softmax.

    float* out = (float*)d_out;
    float* out_att = out + BB * DD;

    cudaFuncSetAttribute(k_gemm, cudaFuncAttributeMaxDynamicSharedMemorySize,
                         GEMM_SMEM);

    k_split<<<512, 512>>>(W_enc);
    k_vsplit<<<(BB * TT * DD) / (4 * 256), 256>>>(value);
    k_dec<<<BB, DD>>>(query, W_dec, b_enc);
    k_conv<<<dim3(TT / 256, BB), 256>>>(att_prev, W_conv);
    k_gemm<<<dim3(NBLK, TT / 128, BB), 256, GEMM_SMEM>>>(W_att, w_g);
    k_softmax<<<BB, 256>>>(lens, out_att);
    k_ctx_part<<<dim3(8, BB), 128>>>(value, out_att);
    k_ctx_final<<<BB * DD / 256, 256>>>(out);
}

// round 10
// speedup vs baseline: 1.5727x; 1.4196x over previous
#include <cuda_runtime.h>
#include <cuda_fp16.h>
#include <math.h>

#define BB 16
#define TT 4096
#define DD 512
#define CCH 10
#define FWD 100
#define KW 201          // 2*FW+1
#define NBLK 4          // N split: 4 tiles of 128 columns
#define TCH 16          // context T-chunks

// ---------------- device scratch (static, allowed) ----------------
__device__ __align__(16) __half g_Wh[DD * DD];                  // W_enc fp16
__device__ __align__(16) __half g_Vh[(size_t)BB * TT * DD];     // value fp16
__device__ float g_dec[BB * DD];                 // dec projection + b_enc
__device__ float g_conv[BB * TT * CCH];          // conv features [b][t][c]
__device__ float g_epart[NBLK * BB * TT];        // partial logits per N-block
__device__ float g_ctxpart[TCH * BB * DD];       // context partials per T-chunk

// ---------------- helpers ----------------
__device__ __forceinline__ float tanh_fast(float x) {
    float ax = fabsf(x);
    float z = __expf(-2.0f * ax);
    float t = __fdividef(1.0f - z, 1.0f + z);
    return copysignf(t, x);
}

// fp16 MMA, fp32 accum. NOT volatile: ptxas may interleave freely.
__device__ __forceinline__ void mma_f16(float* d, const unsigned* a,
                                        unsigned b0, unsigned b1) {
    asm("mma.sync.aligned.m16n8k16.row.col.f32.f16.f16.f32 "
        "{%0,%1,%2,%3}, {%4,%5,%6,%7}, {%8,%9}, {%0,%1,%2,%3};\n"
        : "+f"(d[0]), "+f"(d[1]), "+f"(d[2]), "+f"(d[3])
        : "r"(a[0]), "r"(a[1]), "r"(a[2]), "r"(a[3]), "r"(b0), "r"(b1));
}

__device__ __forceinline__ void ldsm4(unsigned* r, unsigned addr) {
    asm volatile("ldmatrix.sync.aligned.m8n8.x4.shared.b16 {%0,%1,%2,%3}, [%4];\n"
                 : "=r"(r[0]), "=r"(r[1]), "=r"(r[2]), "=r"(r[3]) : "r"(addr));
}

#define CP_ASYNC16(sm, gm) \
    asm volatile("cp.async.cg.shared.global [%0], [%1], 16;\n" :: "r"(sm), "l"(gm))
#define CP_COMMIT() asm volatile("cp.async.commit_group;\n")
#define CP_WAIT(n)  asm volatile("cp.async.wait_group %0;\n" :: "n"(n))

// ---------------- kernel 1: W_enc -> fp16 ----------------
__global__ void k_split(const float* __restrict__ W) {
    int i = blockIdx.x * blockDim.x + threadIdx.x;
    g_Wh[i] = __float2half_rn(W[i]);
}

// ---------------- kernel 1b: value -> fp16 ----------------
__global__ void __launch_bounds__(256) k_vconv(const float* __restrict__ v) {
    size_t i = ((size_t)blockIdx.x * 256 + threadIdx.x) * 4;
    float4 x = *(const float4*)(v + i);
    __half2 p0 = __floats2half2_rn(x.x, x.y);
    __half2 p1 = __floats2half2_rn(x.z, x.w);
    *reinterpret_cast<uint2*>(g_Vh + i) =
        make_uint2(*(unsigned*)&p0, *(unsigned*)&p1);
}

// ---------------- kernel 2: dec projection + b_enc ----------------
__global__ void k_dec(const float* __restrict__ query,
                      const float* __restrict__ Wdec,
                      const float* __restrict__ b_enc) {
    __shared__ float q[DD];
    int b = blockIdx.x;
    int e = threadIdx.x;
    q[e] = query[b * DD + e];
    __syncthreads();
    float acc = b_enc[e];
    const float* wr = Wdec + e * DD;
#pragma unroll 8
    for (int d = 0; d < DD; ++d) acc += q[d] * wr[d];
    g_dec[b * DD + e] = acc;
}

// ---------------- kernel 3: location conv (att_prev -> [b][t][10]) ------
__global__ void k_conv(const float* __restrict__ att_prev,
                       const float* __restrict__ Wconv) {
    __shared__ float win[256 + 2 * FWD];
    __shared__ float wc[CCH * KW];
    int t0 = blockIdx.x * 256;
    int b = blockIdx.y;
    int tid = threadIdx.x;                 // 256
    for (int i = tid; i < 256 + 2 * FWD; i += 256) {
        int gidx = t0 - FWD + i;
        win[i] = (gidx >= 0 && gidx < TT) ? att_prev[b * TT + gidx] : 0.f;
    }
    for (int i = tid; i < CCH * KW; i += 256) wc[i] = Wconv[i];
    __syncthreads();
    float acc[CCH];
#pragma unroll
    for (int c = 0; c < CCH; ++c) acc[c] = 0.f;
    for (int h = 0; h < KW; ++h) {
        float x = win[tid + h];
#pragma unroll
        for (int c = 0; c < CCH; ++c) acc[c] += x * wc[c * KW + h];
    }
    float* o = &g_conv[(size_t)(b * TT + t0 + tid) * CCH];
#pragma unroll
    for (int c = 0; c < CCH; ++c) o[c] = acc[c];
}

// ---------------- kernel 4: fused 1-term fp16 GEMM + epilogue -----------
// 128(t) x 128(e) tile, KC=32, 4-stage cp.async, 1 barrier/iter,
// 256 threads (8 warps, 4m x 2n), 2 CTAs/SM (regs <= 128, smem 80KB).
#define KC 32
#define NCHUNK (DD / KC)       // 16
#define NSTAGE 4
#define ROWU 20                // padded row stride in uints (80 B)
#define ARR_BYTES (128u * ROWU * 4u)      // 10240 B per array
#define STAGE_BYTES (2u * ARR_BYTES)      // 20480 B: A|B
#define GEMM_SMEM (NSTAGE * STAGE_BYTES)  // 81920 B

__global__ void __launch_bounds__(256, 2)
k_gemm(const float* __restrict__ Watt,
       const float* __restrict__ wg) {
    extern __shared__ __align__(16) char dsm[];
    int tid = threadIdx.x;
    int b = blockIdx.z;
    int e0 = blockIdx.x * 128;             // N-block fastest -> A L2 reuse
    int t0 = blockIdx.y * 128;
    int lane = tid & 31, warp = tid >> 5;
    int wm = warp & 3, wn = warp >> 2;     // 4m x 2n warps
    int g = lane >> 2, c = lane & 3;

    float acc[2][8][4];
#pragma unroll
    for (int mt = 0; mt < 2; ++mt)
#pragma unroll
        for (int nt = 0; nt < 8; ++nt)
#pragma unroll
            for (int q = 0; q < 4; ++q) acc[mt][nt][q] = 0.f;

    unsigned sbase = (unsigned)__cvta_generic_to_shared(dsm);

    // cp.async mapping: thread -> row = tid>>1, seg pair = (tid&1)*2
    int row0 = tid >> 1, hseg = (tid & 1) * 2;   // segs {0,1} or {2,3}
    unsigned soff = (unsigned)(row0 * ROWU * 4 + hseg * 16);
    const __half* gA = g_Vh + ((size_t)(b * TT + t0 + row0)) * DD + hseg * 8;
    const __half* gB = g_Wh + (size_t)(e0 + row0) * DD + hseg * 8;

#define ISSUE_STAGE(s, k0)                                                    \
    do {                                                                      \
        unsigned sb = sbase + (unsigned)(s) * STAGE_BYTES + soff;             \
        CP_ASYNC16(sb, gA + (k0));                                            \
        CP_ASYNC16(sb + 16, gA + (k0) + 8);                                   \
        CP_ASYNC16(sb + ARR_BYTES, gB + (k0));                                \
        CP_ASYNC16(sb + ARR_BYTES + 16, gB + (k0) + 8);                       \
    } while (0)

    int lr = ((lane >> 3) & 1) * 8 + (lane & 7);
    int lc = ((lane >> 4) & 1) * 4;

    ISSUE_STAGE(0, 0); CP_COMMIT();
    ISSUE_STAGE(1, KC); CP_COMMIT();
    ISSUE_STAGE(2, 2 * KC); CP_COMMIT();

    for (int it = 0; it < NCHUNK; ++it) {
        CP_WAIT(2);
        __syncthreads();
        unsigned stb = sbase + (unsigned)(it & 3) * STAGE_BYTES;

#pragma unroll
        for (int ks = 0; ks < 2; ++ks) {
            unsigned kso = (unsigned)(ks * 32);    // 8 uints = 32 bytes
            unsigned af[2][4], bf[4][4];
#pragma unroll
            for (int mt = 0; mt < 2; ++mt) {
                unsigned ao = stb +
                    (unsigned)((wm * 32 + mt * 16 + lr) * ROWU * 4 + lc * 4) + kso;
                ldsm4(af[mt], ao);
            }
#pragma unroll
            for (int ntp = 0; ntp < 4; ++ntp) {
                unsigned bo = stb + ARR_BYTES +
                    (unsigned)((wn * 64 + ntp * 16 + lr) * ROWU * 4 + lc * 4) + kso;
                ldsm4(bf[ntp], bo);
            }
            // nt-major: consecutive MMAs hit different accumulators
#pragma unroll
            for (int ntp = 0; ntp < 4; ++ntp)
#pragma unroll
                for (int sub = 0; sub < 2; ++sub)
#pragma unroll
                    for (int mt = 0; mt < 2; ++mt)
                        mma_f16(acc[mt][ntp * 2 + sub], af[mt],
                                bf[ntp][sub], bf[ntp][2 + sub]);
        }
        if (it + 3 < NCHUNK) ISSUE_STAGE((it + 3) & 3, (it + 3) * KC);
        CP_COMMIT();
    }
    __syncthreads();   // all stages consumed; safe to overlay epilogue

    // ---- epilogue smem overlay on dynamic smem ----
    float* econv = (float*)dsm;              // [128][10]
    float* ewatt = econv + 1280;             // [128][10]
    float* edec  = ewatt + 1280;             // [128]
    float* ewg   = edec + 128;               // [128]
    float* ered  = ewg + 128;                // [128][2]

    for (int i = tid; i < 1280; i += 256) {
        int row = i / 10, cc = i - row * 10;
        econv[i] = g_conv[(size_t)(b * TT + t0 + row) * CCH + cc];
        ewatt[i] = Watt[(e0 + row) * CCH + cc];
    }
    if (tid < 128) {
        edec[tid] = g_dec[b * DD + e0 + tid];
        ewg[tid] = wg[e0 + tid];
    }
    __syncthreads();

    float rowsum[2][2];
#pragma unroll
    for (int mt = 0; mt < 2; ++mt)
#pragma unroll
        for (int rr = 0; rr < 2; ++rr) {
            int rowl = wm * 32 + mt * 16 + rr * 8 + g;
            float sacc = 0.f;
#pragma unroll
            for (int nt = 0; nt < 8; ++nt)
#pragma unroll
                for (int q = 0; q < 2; ++q) {
                    int el = wn * 64 + nt * 8 + 2 * c + q;
                    float v = acc[mt][nt][rr * 2 + q] + edec[el];
#pragma unroll
                    for (int cc = 0; cc < CCH; ++cc)
                        v += econv[rowl * 10 + cc] * ewatt[el * 10 + cc];
                    sacc += ewg[el] * tanh_fast(v);
                }
            rowsum[mt][rr] = sacc;
        }
#pragma unroll
    for (int mt = 0; mt < 2; ++mt)
#pragma unroll
        for (int rr = 0; rr < 2; ++rr) {
            float v = rowsum[mt][rr];
            v += __shfl_xor_sync(0xffffffffu, v, 1);
            v += __shfl_xor_sync(0xffffffffu, v, 2);
            rowsum[mt][rr] = v;
        }
    if (c == 0) {
#pragma unroll
        for (int mt = 0; mt < 2; ++mt)
#pragma unroll
            for (int rr = 0; rr < 2; ++rr)
                ered[(wm * 32 + mt * 16 + rr * 8 + g) * 2 + wn] = rowsum[mt][rr];
    }
    __syncthreads();
    if (tid < 128) {
        float val = ered[tid * 2] + ered[tid * 2 + 1];
        g_epart[((size_t)blockIdx.x * BB + b) * TT + t0 + tid] = val;
    }
}

// ---------------- kernel 5: masked sharpened softmax ----------------
__global__ void k_softmax(const int* __restrict__ lens,
                          float* __restrict__ out_att) {
    int b = blockIdx.x;
    int tid = threadIdx.x;            // 256
    int len = lens[b];
    __shared__ float sred[256];
    float ev[16];
    float lmax = -INFINITY;
#pragma unroll
    for (int i = 0; i < 16; ++i) {
        int t = tid + i * 256;
        float e = g_epart[(0 * BB + b) * TT + t] +
                  g_epart[(1 * BB + b) * TT + t] +
                  g_epart[(2 * BB + b) * TT + t] +
                  g_epart[(3 * BB + b) * TT + t];
        e *= 2.0f;                    // sharpening
        ev[i] = (t < len) ? e : -INFINITY;
        lmax = fmaxf(lmax, ev[i]);
    }
    sred[tid] = lmax;
    __syncthreads();
    for (int s = 128; s > 0; s >>= 1) {
        if (tid < s) sred[tid] = fmaxf(sred[tid], sred[tid + s]);
        __syncthreads();
    }
    float m = sred[0];
    __syncthreads();
    float lsum = 0.f;
#pragma unroll
    for (int i = 0; i < 16; ++i) {
        float p = expf(ev[i] - m);
        ev[i] = p;
        lsum += p;
    }
    sred[tid] = lsum;
    __syncthreads();
    for (int s = 128; s > 0; s >>= 1) {
        if (tid < s) sred[tid] += sred[tid + s];
        __syncthreads();
    }
    float inv = 1.f / sred[0];
#pragma unroll
    for (int i = 0; i < 16; ++i)
        out_att[b * TT + tid + i * 256] = ev[i] * inv;
}

// ---------------- kernel 6/7: context = value^T @ weights ----------------
__global__ void __launch_bounds__(128) k_ctx_part(const float* __restrict__ value,
                                                  const float* __restrict__ att) {
    int tch = blockIdx.x, b = blockIdx.y;
    int d4 = threadIdx.x * 4;
    const float* vb = value + (size_t)b * TT * DD;
    const float* ab = att + b * TT;
    float a0 = 0.f, a1 = 0.f, a2 = 0.f, a3 = 0.f;
    int tbase = tch * (TT / TCH);
#pragma unroll 4
    for (int t = tbase; t < tbase + TT / TCH; ++t) {
        float4 v = *(const float4*)(vb + (size_t)t * DD + d4);
        float w = __ldg(ab + t);
        a0 += v.x * w; a1 += v.y * w; a2 += v.z * w; a3 += v.w * w;
    }
    float* o = &g_ctxpart[((size_t)tch * BB + b) * DD + d4];
    o[0] = a0; o[1] = a1; o[2] = a2; o[3] = a3;
}

__global__ void k_ctx_final(float* __restrict__ out) {
    int idx = blockIdx.x * 256 + threadIdx.x;
    float v = 0.f;
#pragma unroll
    for (int p = 0; p < TCH; ++p) v += g_ctxpart[p * BB * DD + idx];
    out[idx] = v;
}

// ---------------- launch ----------------
extern "C" void kernel_launch(void* const* d_in, const int* in_sizes, int n_in,
                              void* d_out, int out_size) {
    const float* value    = (const float*)d_in[0];
    const float* query    = (const float*)d_in[1];
    const int*   lens     = (const int*)d_in[2];
    const float* att_prev = (const float*)d_in[3];
    const float* W_enc    = (const float*)d_in[4];
    const float* b_enc    = (const float*)d_in[5];
    const float* W_dec    = (const float*)d_in[6];
    const float* W_att    = (const float*)d_in[7];
    const float* W_conv   = (const float*)d_in[8];
    const float* w_g      = (const float*)d_in[9];
    // d_in[10] = b_g: uniform logit shift, cancels in softmax.

    float* out = (float*)d_out;
    float* out_att = out + BB * DD;

    cudaFuncSetAttribute(k_gemm, cudaFuncAttributeMaxDynamicSharedMemorySize,
                         GEMM_SMEM);

    k_split<<<512, 512>>>(W_enc);
    k_vconv<<<(BB * TT * DD) / (4 * 256), 256>>>(value);
    k_dec<<<BB, DD>>>(query, W_dec, b_enc);
    k_conv<<<dim3(TT / 256, BB), 256>>>(att_prev, W_conv);
    k_gemm<<<dim3(NBLK, TT / 128, BB), 256, GEMM_SMEM>>>(W_att, w_g);
    k_softmax<<<BB, 256>>>(lens, out_att);
    k_ctx_part<<<dim3(TCH, BB), 128>>>(value, out_att);
    k_ctx_final<<<BB * DD / 256, 256>>>(out);
}

// round 12
// speedup vs baseline: 1.7199x; 1.0936x over previous
#include <cuda_runtime.h>
#include <cuda_fp16.h>
#include <math.h>

#define BB 16
#define TT 4096
#define DD 512
#define CCH 10
#define FWD 100
#define KW 201          // 2*FW+1
#define NBLK 8          // N split: 8 tiles of 64 columns
#define TCH 16          // context T-chunks

// ---------------- device scratch (static, allowed) ----------------
__device__ __align__(16) __half g_Wh[DD * DD];                  // W_enc fp16
__device__ __align__(16) __half g_Vh[(size_t)BB * TT * DD];     // value fp16
__device__ float g_dec[BB * DD];                 // dec projection + b_enc
__device__ float g_conv[BB * TT * CCH];          // conv features [b][t][c]
__device__ float g_epart[NBLK * BB * TT];        // partial logits per N-block
__device__ float g_ctxpart[TCH * BB * DD];       // context partials per T-chunk

// ---------------- helpers ----------------
__device__ __forceinline__ float tanh_fast(float x) {
    float ax = fabsf(x);
    float z = __expf(-2.0f * ax);
    float t = __fdividef(1.0f - z, 1.0f + z);
    return copysignf(t, x);
}

// fp16 MMA, fp32 accum. NOT volatile: ptxas may interleave freely.
__device__ __forceinline__ void mma_f16(float* d, const unsigned* a,
                                        unsigned b0, unsigned b1) {
    asm("mma.sync.aligned.m16n8k16.row.col.f32.f16.f16.f32 "
        "{%0,%1,%2,%3}, {%4,%5,%6,%7}, {%8,%9}, {%0,%1,%2,%3};\n"
        : "+f"(d[0]), "+f"(d[1]), "+f"(d[2]), "+f"(d[3])
        : "r"(a[0]), "r"(a[1]), "r"(a[2]), "r"(a[3]), "r"(b0), "r"(b1));
}

__device__ __forceinline__ void ldsm4(unsigned* r, unsigned addr) {
    asm volatile("ldmatrix.sync.aligned.m8n8.x4.shared.b16 {%0,%1,%2,%3}, [%4];\n"
                 : "=r"(r[0]), "=r"(r[1]), "=r"(r[2]), "=r"(r[3]) : "r"(addr));
}

#define CP_ASYNC16(sm, gm) \
    asm volatile("cp.async.cg.shared.global [%0], [%1], 16;\n" :: "r"(sm), "l"(gm))
#define CP_COMMIT() asm volatile("cp.async.commit_group;\n")
#define CP_WAIT(n)  asm volatile("cp.async.wait_group %0;\n" :: "n"(n))

// ---------------- kernel 1: W_enc -> fp16 ----------------
__global__ void k_split(const float* __restrict__ W) {
    int i = blockIdx.x * blockDim.x + threadIdx.x;
    g_Wh[i] = __float2half_rn(W[i]);
}

// ---------------- kernel 1b: value -> fp16 ----------------
__global__ void __launch_bounds__(256) k_vconv(const float* __restrict__ v) {
    size_t i = ((size_t)blockIdx.x * 256 + threadIdx.x) * 4;
    float4 x = *(const float4*)(v + i);
    __half2 p0 = __floats2half2_rn(x.x, x.y);
    __half2 p1 = __floats2half2_rn(x.z, x.w);
    *reinterpret_cast<uint2*>(g_Vh + i) =
        make_uint2(*(unsigned*)&p0, *(unsigned*)&p1);
}

// ---------------- kernel 2: dec projection + b_enc ----------------
__global__ void k_dec(const float* __restrict__ query,
                      const float* __restrict__ Wdec,
                      const float* __restrict__ b_enc) {
    __shared__ float q[DD];
    int b = blockIdx.x;
    int e = threadIdx.x;
    q[e] = query[b * DD + e];
    __syncthreads();
    float acc = b_enc[e];
    const float* wr = Wdec + e * DD;
#pragma unroll 8
    for (int d = 0; d < DD; ++d) acc += q[d] * wr[d];
    g_dec[b * DD + e] = acc;
}

// ---------------- kernel 3: location conv (att_prev -> [b][t][10]) ------
__global__ void k_conv(const float* __restrict__ att_prev,
                       const float* __restrict__ Wconv) {
    __shared__ float win[256 + 2 * FWD];
    __shared__ float wc[CCH * KW];
    int t0 = blockIdx.x * 256;
    int b = blockIdx.y;
    int tid = threadIdx.x;                 // 256
    for (int i = tid; i < 256 + 2 * FWD; i += 256) {
        int gidx = t0 - FWD + i;
        win[i] = (gidx >= 0 && gidx < TT) ? att_prev[b * TT + gidx] : 0.f;
    }
    for (int i = tid; i < CCH * KW; i += 256) wc[i] = Wconv[i];
    __syncthreads();
    float acc[CCH];
#pragma unroll
    for (int c = 0; c < CCH; ++c) acc[c] = 0.f;
    for (int h = 0; h < KW; ++h) {
        float x = win[tid + h];
#pragma unroll
        for (int c = 0; c < CCH; ++c) acc[c] += x * wc[c * KW + h];
    }
    float* o = &g_conv[(size_t)(b * TT + t0 + tid) * CCH];
#pragma unroll
    for (int c = 0; c < CCH; ++c) o[c] = acc[c];
}

// ---------------- kernel 4: fused 1-term fp16 GEMM + epilogue -----------
// 128(t) x 64(e) tile, KC=32, 4-stage cp.async, 1 barrier/iter,
// 256 threads (8 warps, 4m x 2n => warp tile 32x32), 3 CTAs/SM (60KB smem).
#define KC 32
#define NCHUNK (DD / KC)       // 16
#define NSTAGE 4
#define ROWU 20                // padded row stride in uints (80 B)
#define ARR_A (128u * ROWU * 4u)          // 10240 B (A: 128 rows)
#define ARR_B (64u * ROWU * 4u)           // 5120 B  (B: 64 rows)
#define STAGE_BYTES (ARR_A + ARR_B)       // 15360 B
#define GEMM_SMEM (NSTAGE * STAGE_BYTES)  // 61440 B

__global__ void __launch_bounds__(256, 3)
k_gemm(const float* __restrict__ Watt,
       const float* __restrict__ wg) {
    extern __shared__ __align__(16) char dsm[];
    int tid = threadIdx.x;
    int b = blockIdx.z;
    int e0 = blockIdx.x * 64;              // N-block fastest -> A L2 reuse
    int t0 = blockIdx.y * 128;
    int lane = tid & 31, warp = tid >> 5;
    int wm = warp & 3, wn = warp >> 2;     // 4m x 2n warps, 32x32 warp tile
    int g = lane >> 2, c = lane & 3;

    float acc[2][4][4];
#pragma unroll
    for (int mt = 0; mt < 2; ++mt)
#pragma unroll
        for (int nt = 0; nt < 4; ++nt)
#pragma unroll
            for (int q = 0; q < 4; ++q) acc[mt][nt][q] = 0.f;

    unsigned sbase = (unsigned)__cvta_generic_to_shared(dsm);

    // cp.async A: row = tid>>1 (0..127), 32B per thread
    int rowA = tid >> 1, hsegA = (tid & 1) * 2;
    unsigned soffA = (unsigned)(rowA * ROWU * 4 + hsegA * 16);
    const __half* gA = g_Vh + ((size_t)(b * TT + t0 + rowA)) * DD + hsegA * 8;
    // cp.async B: row = tid>>2 (0..63), 16B per thread
    int rowB = tid >> 2, segB = tid & 3;
    unsigned soffB = (unsigned)(ARR_A + rowB * ROWU * 4 + segB * 16);
    const __half* gB = g_Wh + (size_t)(e0 + rowB) * DD + segB * 8;

#define ISSUE_STAGE(s, k0)                                                    \
    do {                                                                      \
        unsigned sb = sbase + (unsigned)(s) * STAGE_BYTES;                    \
        CP_ASYNC16(sb + soffA, gA + (k0));                                    \
        CP_ASYNC16(sb + soffA + 16, gA + (k0) + 8);                           \
        CP_ASYNC16(sb + soffB, gB + (k0));                                    \
    } while (0)

    int lr = ((lane >> 3) & 1) * 8 + (lane & 7);
    int lc = ((lane >> 4) & 1) * 4;

    ISSUE_STAGE(0, 0); CP_COMMIT();
    ISSUE_STAGE(1, KC); CP_COMMIT();
    ISSUE_STAGE(2, 2 * KC); CP_COMMIT();

    for (int it = 0; it < NCHUNK; ++it) {
        CP_WAIT(2);
        __syncthreads();
        unsigned stb = sbase + (unsigned)(it & 3) * STAGE_BYTES;

#pragma unroll
        for (int ks = 0; ks < 2; ++ks) {
            unsigned kso = (unsigned)(ks * 32);    // 8 uints = 32 bytes
            unsigned af[2][4], bf[2][4];
#pragma unroll
            for (int mt = 0; mt < 2; ++mt) {
                unsigned ao = stb +
                    (unsigned)((wm * 32 + mt * 16 + lr) * ROWU * 4 + lc * 4) + kso;
                ldsm4(af[mt], ao);
            }
#pragma unroll
            for (int ntp = 0; ntp < 2; ++ntp) {
                unsigned bo = stb + ARR_A +
                    (unsigned)((wn * 32 + ntp * 16 + lr) * ROWU * 4 + lc * 4) + kso;
                ldsm4(bf[ntp], bo);
            }
            // nt-major: consecutive MMAs hit different accumulators
#pragma unroll
            for (int ntp = 0; ntp < 2; ++ntp)
#pragma unroll
                for (int sub = 0; sub < 2; ++sub)
#pragma unroll
                    for (int mt = 0; mt < 2; ++mt)
                        mma_f16(acc[mt][ntp * 2 + sub], af[mt],
                                bf[ntp][sub], bf[ntp][2 + sub]);
        }
        if (it + 3 < NCHUNK) ISSUE_STAGE((it + 3) & 3, (it + 3) * KC);
        CP_COMMIT();
    }
    __syncthreads();   // all stages consumed; safe to overlay epilogue

    // ---- epilogue smem overlay on dynamic smem ----
    float* econv = (float*)dsm;              // [128][10]
    float* ewatt = econv + 1280;             // [64][10]
    float* edec  = ewatt + 640;              // [64]
    float* ewg   = edec + 64;                // [64]
    float* ered  = ewg + 64;                 // [128][2]

    for (int i = tid; i < 1280; i += 256) {
        int row = i / 10, cc = i - row * 10;
        econv[i] = g_conv[(size_t)(b * TT + t0 + row) * CCH + cc];
    }
    for (int i = tid; i < 640; i += 256) {
        int row = i / 10, cc = i - row * 10;
        ewatt[i] = Watt[(e0 + row) * CCH + cc];
    }
    if (tid < 64) {
        edec[tid] = g_dec[b * DD + e0 + tid];
        ewg[tid] = wg[e0 + tid];
    }
    __syncthreads();

    float rowsum[2][2];
#pragma unroll
    for (int mt = 0; mt < 2; ++mt)
#pragma unroll
        for (int rr = 0; rr < 2; ++rr) {
            int rowl = wm * 32 + mt * 16 + rr * 8 + g;
            float sacc = 0.f;
#pragma unroll
            for (int nt = 0; nt < 4; ++nt)
#pragma unroll
                for (int q = 0; q < 2; ++q) {
                    int el = wn * 32 + nt * 8 + 2 * c + q;
                    float v = acc[mt][nt][rr * 2 + q] + edec[el];
#pragma unroll
                    for (int cc = 0; cc < CCH; ++cc)
                        v += econv[rowl * 10 + cc] * ewatt[el * 10 + cc];
                    sacc += ewg[el] * tanh_fast(v);
                }
            rowsum[mt][rr] = sacc;
        }
#pragma unroll
    for (int mt = 0; mt < 2; ++mt)
#pragma unroll
        for (int rr = 0; rr < 2; ++rr) {
            float v = rowsum[mt][rr];
            v += __shfl_xor_sync(0xffffffffu, v, 1);
            v += __shfl_xor_sync(0xffffffffu, v, 2);
            rowsum[mt][rr] = v;
        }
    if (c == 0) {
#pragma unroll
        for (int mt = 0; mt < 2; ++mt)
#pragma unroll
            for (int rr = 0; rr < 2; ++rr)
                ered[(wm * 32 + mt * 16 + rr * 8 + g) * 2 + wn] = rowsum[mt][rr];
    }
    __syncthreads();
    if (tid < 128) {
        float val = ered[tid * 2] + ered[tid * 2 + 1];
        g_epart[((size_t)blockIdx.x * BB + b) * TT + t0 + tid] = val;
    }
}

// ---------------- kernel 5: masked sharpened softmax ----------------
__global__ void k_softmax(const int* __restrict__ lens,
                          float* __restrict__ out_att) {
    int b = blockIdx.x;
    int tid = threadIdx.x;            // 256
    int len = lens[b];
    __shared__ float sred[256];
    float ev[16];
    float lmax = -INFINITY;
#pragma unroll
    for (int i = 0; i < 16; ++i) {
        int t = tid + i * 256;
        float e = 0.f;
#pragma unroll
        for (int p = 0; p < NBLK; ++p)
            e += g_epart[(p * BB + b) * TT + t];
        e *= 2.0f;                    // sharpening
        ev[i] = (t < len) ? e : -INFINITY;
        lmax = fmaxf(lmax, ev[i]);
    }
    sred[tid] = lmax;
    __syncthreads();
    for (int s = 128; s > 0; s >>= 1) {
        if (tid < s) sred[tid] = fmaxf(sred[tid], sred[tid + s]);
        __syncthreads();
    }
    float m = sred[0];
    __syncthreads();
    float lsum = 0.f;
#pragma unroll
    for (int i = 0; i < 16; ++i) {
        float p = expf(ev[i] - m);
        ev[i] = p;
        lsum += p;
    }
    sred[tid] = lsum;
    __syncthreads();
    for (int s = 128; s > 0; s >>= 1) {
        if (tid < s) sred[tid] += sred[tid + s];
        __syncthreads();
    }
    float inv = 1.f / sred[0];
#pragma unroll
    for (int i = 0; i < 16; ++i)
        out_att[b * TT + tid + i * 256] = ev[i] * inv;
}

// ---------------- kernel 6/7: context = value^T @ weights ----------------
__global__ void __launch_bounds__(128) k_ctx_part(const float* __restrict__ value,
                                                  const float* __restrict__ att) {
    int tch = blockIdx.x, b = blockIdx.y;
    int d4 = threadIdx.x * 4;
    const float* vb = value + (size_t)b * TT * DD;
    const float* ab = att + b * TT;
    float a0 = 0.f, a1 = 0.f, a2 = 0.f, a3 = 0.f;
    int tbase = tch * (TT / TCH);
#pragma unroll 4
    for (int t = tbase; t < tbase + TT / TCH; ++t) {
        float4 v = *(const float4*)(vb + (size_t)t * DD + d4);
        float w = __ldg(ab + t);
        a0 += v.x * w; a1 += v.y * w; a2 += v.z * w; a3 += v.w * w;
    }
    float* o = &g_ctxpart[((size_t)tch * BB + b) * DD + d4];
    o[0] = a0; o[1] = a1; o[2] = a2; o[3] = a3;
}

__global__ void k_ctx_final(float* __restrict__ out) {
    int idx = blockIdx.x * 256 + threadIdx.x;
    float v = 0.f;
#pragma unroll
    for (int p = 0; p < TCH; ++p) v += g_ctxpart[p * BB * DD + idx];
    out[idx] = v;
}

// ---------------- launch ----------------
extern "C" void kernel_launch(void* const* d_in, const int* in_sizes, int n_in,
                              void* d_out, int out_size) {
    const float* value    = (const float*)d_in[0];
    const float* query    = (const float*)d_in[1];
    const int*   lens     = (const int*)d_in[2];
    const float* att_prev = (const float*)d_in[3];
    const float* W_enc    = (const float*)d_in[4];
    const float* b_enc    = (const float*)d_in[5];
    const float* W_dec    = (const float*)d_in[6];
    const float* W_att    = (const float*)d_in[7];
    const float* W_conv   = (const float*)d_in[8];
    const float* w_g      = (const float*)d_in[9];
    // d_in[10] = b_g: uniform logit shift, cancels in softmax.

    float* out = (float*)d_out;
    float* out_att = out + BB * DD;

    cudaFuncSetAttribute(k_gemm, cudaFuncAttributeMaxDynamicSharedMemorySize,
                         GEMM_SMEM);

    k_split<<<512, 512>>>(W_enc);
    k_vconv<<<(BB * TT * DD) / (4 * 256), 256>>>(value);
    k_dec<<<BB, DD>>>(query, W_dec, b_enc);
    k_conv<<<dim3(TT / 256, BB), 256>>>(att_prev, W_conv);
    k_gemm<<<dim3(NBLK, TT / 128, BB), 256, GEMM_SMEM>>>(W_att, w_g);
    k_softmax<<<BB, 256>>>(lens, out_att);
    k_ctx_part<<<dim3(TCH, BB), 128>>>(value, out_att);
    k_ctx_final<<<BB * DD / 256, 256>>>(out);
}

// round 13
// speedup vs baseline: 1.8145x; 1.0550x over previous
#include <cuda_runtime.h>
#include <cuda_fp16.h>
#include <math.h>

#define BB 16
#define TT 4096
#define DD 512
#define CCH 10
#define FWD 100
#define KW 201          // 2*FW+1
#define NBLK 8          // N split: 8 tiles of 64 columns
#define TCH 32          // context T-chunks

// ---------------- device scratch (static, allowed) ----------------
__device__ __align__(16) __half g_Wh[DD * DD];                  // W_enc fp16
__device__ __align__(16) __half g_Vh[(size_t)BB * TT * DD];     // value fp16
__device__ float g_dec[BB * DD];                 // dec projection + b_enc
__device__ float g_conv[BB * TT * CCH];          // conv features [b][t][c]
__device__ float g_epart[NBLK * BB * TT];        // partial logits per N-block
__device__ float g_ctxpart[TCH * BB * DD];       // context partials per T-chunk

// ---------------- helpers ----------------
__device__ __forceinline__ float tanh_fast(float x) {
    float ax = fabsf(x);
    float z = __expf(-2.0f * ax);
    float t = __fdividef(1.0f - z, 1.0f + z);
    return copysignf(t, x);
}

// fp16 MMA, fp32 accum. NOT volatile: ptxas may interleave freely.
__device__ __forceinline__ void mma_f16(float* d, const unsigned* a,
                                        unsigned b0, unsigned b1) {
    asm("mma.sync.aligned.m16n8k16.row.col.f32.f16.f16.f32 "
        "{%0,%1,%2,%3}, {%4,%5,%6,%7}, {%8,%9}, {%0,%1,%2,%3};\n"
        : "+f"(d[0]), "+f"(d[1]), "+f"(d[2]), "+f"(d[3])
        : "r"(a[0]), "r"(a[1]), "r"(a[2]), "r"(a[3]), "r"(b0), "r"(b1));
}

__device__ __forceinline__ void ldsm4(unsigned* r, unsigned addr) {
    asm volatile("ldmatrix.sync.aligned.m8n8.x4.shared.b16 {%0,%1,%2,%3}, [%4];\n"
                 : "=r"(r[0]), "=r"(r[1]), "=r"(r[2]), "=r"(r[3]) : "r"(addr));
}

#define CP_ASYNC16(sm, gm) \
    asm volatile("cp.async.cg.shared.global [%0], [%1], 16;\n" :: "r"(sm), "l"(gm))
#define CP_COMMIT() asm volatile("cp.async.commit_group;\n")
#define CP_WAIT(n)  asm volatile("cp.async.wait_group %0;\n" :: "n"(n))

// ---------------- kernel 1: W_enc -> fp16 ----------------
__global__ void k_split(const float* __restrict__ W) {
    int i = blockIdx.x * blockDim.x + threadIdx.x;
    g_Wh[i] = __float2half_rn(W[i]);
}

// ---------------- kernel 1b: value -> fp16 ----------------
__global__ void __launch_bounds__(256) k_vconv(const float* __restrict__ v) {
    size_t i = ((size_t)blockIdx.x * 256 + threadIdx.x) * 4;
    float4 x = *(const float4*)(v + i);
    __half2 p0 = __floats2half2_rn(x.x, x.y);
    __half2 p1 = __floats2half2_rn(x.z, x.w);
    *reinterpret_cast<uint2*>(g_Vh + i) =
        make_uint2(*(unsigned*)&p0, *(unsigned*)&p1);
}

// ---------------- kernel 2: dec projection + b_enc ----------------
__global__ void k_dec(const float* __restrict__ query,
                      const float* __restrict__ Wdec,
                      const float* __restrict__ b_enc) {
    __shared__ float q[DD];
    int b = blockIdx.x;
    int e = threadIdx.x;
    q[e] = query[b * DD + e];
    __syncthreads();
    float acc = b_enc[e];
    const float* wr = Wdec + e * DD;
#pragma unroll 8
    for (int d = 0; d < DD; ++d) acc += q[d] * wr[d];
    g_dec[b * DD + e] = acc;
}

// ---------------- kernel 3: location conv (att_prev -> [b][t][10]) ------
__global__ void k_conv(const float* __restrict__ att_prev,
                       const float* __restrict__ Wconv) {
    __shared__ float win[256 + 2 * FWD];
    __shared__ float wc[CCH * KW];
    int t0 = blockIdx.x * 256;
    int b = blockIdx.y;
    int tid = threadIdx.x;                 // 256
    for (int i = tid; i < 256 + 2 * FWD; i += 256) {
        int gidx = t0 - FWD + i;
        win[i] = (gidx >= 0 && gidx < TT) ? att_prev[b * TT + gidx] : 0.f;
    }
    for (int i = tid; i < CCH * KW; i += 256) wc[i] = Wconv[i];
    __syncthreads();
    float acc[CCH];
#pragma unroll
    for (int c = 0; c < CCH; ++c) acc[c] = 0.f;
    for (int h = 0; h < KW; ++h) {
        float x = win[tid + h];
#pragma unroll
        for (int c = 0; c < CCH; ++c) acc[c] += x * wc[c * KW + h];
    }
    float* o = &g_conv[(size_t)(b * TT + t0 + tid) * CCH];
#pragma unroll
    for (int c = 0; c < CCH; ++c) o[c] = acc[c];
}

// ---------------- kernel 4: fused 1-term fp16 GEMM + epilogue -----------
// 128(t) x 64(e) tile, KC=32, 3-stage cp.async (depth-2 prefetch),
// 1 barrier/iter, 256 threads (8 warps, 4m x 2n), 4 CTAs/SM (45KB smem).
#define KC 32
#define NCHUNK (DD / KC)       // 16
#define NSTAGE 3
#define ROWU 20                // padded row stride in uints (80 B)
#define ARR_A (128u * ROWU * 4u)          // 10240 B (A: 128 rows)
#define ARR_B (64u * ROWU * 4u)           // 5120 B  (B: 64 rows)
#define STAGE_BYTES (ARR_A + ARR_B)       // 15360 B
#define GEMM_SMEM (NSTAGE * STAGE_BYTES)  // 46080 B

__global__ void __launch_bounds__(256, 4)
k_gemm(const float* __restrict__ Watt,
       const float* __restrict__ wg) {
    extern __shared__ __align__(16) char dsm[];
    int tid = threadIdx.x;
    int b = blockIdx.z;
    int e0 = blockIdx.x * 64;              // N-block fastest -> A L2 reuse
    int t0 = blockIdx.y * 128;
    int lane = tid & 31, warp = tid >> 5;
    int wm = warp & 3, wn = warp >> 2;     // 4m x 2n warps, 32x32 warp tile
    int g = lane >> 2, c = lane & 3;

    float acc[2][4][4];
#pragma unroll
    for (int mt = 0; mt < 2; ++mt)
#pragma unroll
        for (int nt = 0; nt < 4; ++nt)
#pragma unroll
            for (int q = 0; q < 4; ++q) acc[mt][nt][q] = 0.f;

    unsigned sbase = (unsigned)__cvta_generic_to_shared(dsm);

    // cp.async A: row = tid>>1 (0..127), 32B per thread
    int rowA = tid >> 1, hsegA = (tid & 1) * 2;
    unsigned soffA = (unsigned)(rowA * ROWU * 4 + hsegA * 16);
    const __half* gA = g_Vh + ((size_t)(b * TT + t0 + rowA)) * DD + hsegA * 8;
    // cp.async B: row = tid>>2 (0..63), 16B per thread
    int rowB = tid >> 2, segB = tid & 3;
    unsigned soffB = (unsigned)(ARR_A + rowB * ROWU * 4 + segB * 16);
    const __half* gB = g_Wh + (size_t)(e0 + rowB) * DD + segB * 8;

#define ISSUE_STAGE(s, k0)                                                    \
    do {                                                                      \
        unsigned sb = sbase + (unsigned)(s) * STAGE_BYTES;                    \
        CP_ASYNC16(sb + soffA, gA + (k0));                                    \
        CP_ASYNC16(sb + soffA + 16, gA + (k0) + 8);                           \
        CP_ASYNC16(sb + soffB, gB + (k0));                                    \
    } while (0)

    int lr = ((lane >> 3) & 1) * 8 + (lane & 7);
    int lc = ((lane >> 4) & 1) * 4;

    ISSUE_STAGE(0, 0); CP_COMMIT();
    ISSUE_STAGE(1, KC); CP_COMMIT();

    int st = 0;                            // stage index = it % 3
    for (int it = 0; it < NCHUNK; ++it) {
        CP_WAIT(1);
        __syncthreads();
        unsigned stb = sbase + (unsigned)st * STAGE_BYTES;

#pragma unroll
        for (int ks = 0; ks < 2; ++ks) {
            unsigned kso = (unsigned)(ks * 32);    // 8 uints = 32 bytes
            unsigned af[2][4], bf[2][4];
#pragma unroll
            for (int mt = 0; mt < 2; ++mt) {
                unsigned ao = stb +
                    (unsigned)((wm * 32 + mt * 16 + lr) * ROWU * 4 + lc * 4) + kso;
                ldsm4(af[mt], ao);
            }
#pragma unroll
            for (int ntp = 0; ntp < 2; ++ntp) {
                unsigned bo = stb + ARR_A +
                    (unsigned)((wn * 32 + ntp * 16 + lr) * ROWU * 4 + lc * 4) + kso;
                ldsm4(bf[ntp], bo);
            }
            // nt-major: consecutive MMAs hit different accumulators
#pragma unroll
            for (int ntp = 0; ntp < 2; ++ntp)
#pragma unroll
                for (int sub = 0; sub < 2; ++sub)
#pragma unroll
                    for (int mt = 0; mt < 2; ++mt)
                        mma_f16(acc[mt][ntp * 2 + sub], af[mt],
                                bf[ntp][sub], bf[ntp][2 + sub]);
        }
        // reissue the stage consumed LAST iteration (protected by this
        // iteration's __syncthreads): slot (it+2)%3
        if (it + 2 < NCHUNK) {
            int ns = st + 2; if (ns >= 3) ns -= 3;
            ISSUE_STAGE(ns, (it + 2) * KC);
        }
        CP_COMMIT();
        if (++st == 3) st = 0;
    }
    __syncthreads();   // all stages consumed; safe to overlay epilogue

    // ---- epilogue smem overlay on dynamic smem ----
    float* econv = (float*)dsm;              // [128][10]
    float* ewatt = econv + 1280;             // [64][10]
    float* edec  = ewatt + 640;              // [64]
    float* ewg   = edec + 64;                // [64]
    float* ered  = ewg + 64;                 // [128][2]

    for (int i = tid; i < 1280; i += 256) {
        int row = i / 10, cc = i - row * 10;
        econv[i] = g_conv[(size_t)(b * TT + t0 + row) * CCH + cc];
    }
    for (int i = tid; i < 640; i += 256) {
        int row = i / 10, cc = i - row * 10;
        ewatt[i] = Watt[(e0 + row) * CCH + cc];
    }
    if (tid < 64) {
        edec[tid] = g_dec[b * DD + e0 + tid];
        ewg[tid] = wg[e0 + tid];
    }
    __syncthreads();

    float rowsum[2][2];
#pragma unroll
    for (int mt = 0; mt < 2; ++mt)
#pragma unroll
        for (int rr = 0; rr < 2; ++rr) {
            int rowl = wm * 32 + mt * 16 + rr * 8 + g;
            float sacc = 0.f;
#pragma unroll
            for (int nt = 0; nt < 4; ++nt)
#pragma unroll
                for (int q = 0; q < 2; ++q) {
                    int el = wn * 32 + nt * 8 + 2 * c + q;
                    float v = acc[mt][nt][rr * 2 + q] + edec[el];
#pragma unroll
                    for (int cc = 0; cc < CCH; ++cc)
                        v += econv[rowl * 10 + cc] * ewatt[el * 10 + cc];
                    sacc += ewg[el] * tanh_fast(v);
                }
            rowsum[mt][rr] = sacc;
        }
#pragma unroll
    for (int mt = 0; mt < 2; ++mt)
#pragma unroll
        for (int rr = 0; rr < 2; ++rr) {
            float v = rowsum[mt][rr];
            v += __shfl_xor_sync(0xffffffffu, v, 1);
            v += __shfl_xor_sync(0xffffffffu, v, 2);
            rowsum[mt][rr] = v;
        }
    if (c == 0) {
#pragma unroll
        for (int mt = 0; mt < 2; ++mt)
#pragma unroll
            for (int rr = 0; rr < 2; ++rr)
                ered[(wm * 32 + mt * 16 + rr * 8 + g) * 2 + wn] = rowsum[mt][rr];
    }
    __syncthreads();
    if (tid < 128) {
        float val = ered[tid * 2] + ered[tid * 2 + 1];
        g_epart[((size_t)blockIdx.x * BB + b) * TT + t0 + tid] = val;
    }
}

// ---------------- kernel 5: masked sharpened softmax ----------------
__global__ void k_softmax(const int* __restrict__ lens,
                          float* __restrict__ out_att) {
    int b = blockIdx.x;
    int tid = threadIdx.x;            // 256
    int len = lens[b];
    __shared__ float sred[256];
    float ev[16];
    float lmax = -INFINITY;
#pragma unroll
    for (int i = 0; i < 16; ++i) {
        int t = tid + i * 256;
        float e = 0.f;
#pragma unroll
        for (int p = 0; p < NBLK; ++p)
            e += g_epart[(p * BB + b) * TT + t];
        e *= 2.0f;                    // sharpening
        ev[i] = (t < len) ? e : -INFINITY;
        lmax = fmaxf(lmax, ev[i]);
    }
    sred[tid] = lmax;
    __syncthreads();
    for (int s = 128; s > 0; s >>= 1) {
        if (tid < s) sred[tid] = fmaxf(sred[tid], sred[tid + s]);
        __syncthreads();
    }
    float m = sred[0];
    __syncthreads();
    float lsum = 0.f;
#pragma unroll
    for (int i = 0; i < 16; ++i) {
        float p = expf(ev[i] - m);
        ev[i] = p;
        lsum += p;
    }
    sred[tid] = lsum;
    __syncthreads();
    for (int s = 128; s > 0; s >>= 1) {
        if (tid < s) sred[tid] += sred[tid + s];
        __syncthreads();
    }
    float inv = 1.f / sred[0];
#pragma unroll
    for (int i = 0; i < 16; ++i)
        out_att[b * TT + tid + i * 256] = ev[i] * inv;
}

// ---------------- kernel 6/7: context = value^T @ weights ----------------
__global__ void __launch_bounds__(128) k_ctx_part(const float* __restrict__ value,
                                                  const float* __restrict__ att) {
    int tch = blockIdx.x, b = blockIdx.y;
    int d4 = threadIdx.x * 4;
    const float* vb = value + (size_t)b * TT * DD;
    const float* ab = att + b * TT;
    float a0 = 0.f, a1 = 0.f, a2 = 0.f, a3 = 0.f;
    int tbase = tch * (TT / TCH);
#pragma unroll 4
    for (int t = tbase; t < tbase + TT / TCH; ++t) {
        float4 v = *(const float4*)(vb + (size_t)t * DD + d4);
        float w = __ldg(ab + t);
        a0 += v.x * w; a1 += v.y * w; a2 += v.z * w; a3 += v.w * w;
    }
    float* o = &g_ctxpart[((size_t)tch * BB + b) * DD + d4];
    o[0] = a0; o[1] = a1; o[2] = a2; o[3] = a3;
}

__global__ void k_ctx_final(float* __restrict__ out) {
    int idx = blockIdx.x * 256 + threadIdx.x;
    float v = 0.f;
#pragma unroll
    for (int p = 0; p < TCH; ++p) v += g_ctxpart[p * BB * DD + idx];
    out[idx] = v;
}

// ---------------- launch ----------------
extern "C" void kernel_launch(void* const* d_in, const int* in_sizes, int n_in,
                              void* d_out, int out_size) {
    const float* value    = (const float*)d_in[0];
    const float* query    = (const float*)d_in[1];
    const int*   lens     = (const int*)d_in[2];
    const float* att_prev = (const float*)d_in[3];
    const float* W_enc    = (const float*)d_in[4];
    const float* b_enc    = (const float*)d_in[5];
    const float* W_dec    = (const float*)d_in[6];
    const float* W_att    = (const float*)d_in[7];
    const float* W_conv   = (const float*)d_in[8];
    const float* w_g      = (const float*)d_in[9];
    // d_in[10] = b_g: uniform logit shift, cancels in softmax.

    float* out = (float*)d_out;
    float* out_att = out + BB * DD;

    cudaFuncSetAttribute(k_gemm, cudaFuncAttributeMaxDynamicSharedMemorySize,
                         GEMM_SMEM);

    k_split<<<512, 512>>>(W_enc);
    k_vconv<<<(BB * TT * DD) / (4 * 256), 256>>>(value);
    k_dec<<<BB, DD>>>(query, W_dec, b_enc);
    k_conv<<<dim3(TT / 256, BB), 256>>>(att_prev, W_conv);
    k_gemm<<<dim3(NBLK, TT / 128, BB), 256, GEMM_SMEM>>>(W_att, w_g);
    k_softmax<<<BB, 256>>>(lens, out_att);
    k_ctx_part<<<dim3(TCH, BB), 128>>>(value, out_att);
    k_ctx_final<<<BB * DD / 256, 256>>>(out);
}

// round 15
// speedup vs baseline: 1.8908x; 1.0421x over previous
#include <cuda_runtime.h>
#include <cuda_fp16.h>
#include <math.h>

#define BB 16
#define TT 4096
#define DD 512
#define CCH 10
#define FWD 100
#define KW 201          // 2*FW+1
#define NBLK 8          // N split: 8 tiles of 64 columns
#define TCH 32          // context T-chunks

// ---------------- device scratch (static, allowed) ----------------
__device__ __align__(16) __half g_Wh[DD * DD];                  // W_enc fp16
__device__ __align__(16) __half g_Vh[(size_t)BB * TT * DD];     // value fp16
__device__ float g_dec[BB * DD];                 // dec projection + b_enc
__device__ float g_conv[BB * TT * CCH];          // conv features [b][t][c]
__device__ float g_epart[NBLK * BB * TT];        // partial logits per N-block
__device__ float g_ctxpart[TCH * BB * DD];       // context partials per T-chunk

// ---------------- helpers ----------------
__device__ __forceinline__ float tanh_fast(float x) {
    float ax = fabsf(x);
    float z = __expf(-2.0f * ax);
    float t = __fdividef(1.0f - z, 1.0f + z);
    return copysignf(t, x);
}

// fp16 MMA, fp32 accum. NOT volatile: ptxas may interleave freely.
__device__ __forceinline__ void mma_f16(float* d, const unsigned* a,
                                        unsigned b0, unsigned b1) {
    asm("mma.sync.aligned.m16n8k16.row.col.f32.f16.f16.f32 "
        "{%0,%1,%2,%3}, {%4,%5,%6,%7}, {%8,%9}, {%0,%1,%2,%3};\n"
        : "+f"(d[0]), "+f"(d[1]), "+f"(d[2]), "+f"(d[3])
        : "r"(a[0]), "r"(a[1]), "r"(a[2]), "r"(a[3]), "r"(b0), "r"(b1));
}

__device__ __forceinline__ void ldsm4(unsigned* r, unsigned addr) {
    asm volatile("ldmatrix.sync.aligned.m8n8.x4.shared.b16 {%0,%1,%2,%3}, [%4];\n"
                 : "=r"(r[0]), "=r"(r[1]), "=r"(r[2]), "=r"(r[3]) : "r"(addr));
}

#define CP_ASYNC16(sm, gm) \
    asm volatile("cp.async.cg.shared.global [%0], [%1], 16;\n" :: "r"(sm), "l"(gm))
#define CP_COMMIT() asm volatile("cp.async.commit_group;\n")
#define CP_WAIT(n)  asm volatile("cp.async.wait_group %0;\n" :: "n"(n))

// ---------------- kernel 1: merged prologue ----------------
// role by blockIdx.x:
//   [0, 32768)           : value -> fp16  (DRAM-bound stream)
//   [32768, 33792)       : W_enc -> fp16
//   [33792, 34048)       : location conv -> g_conv
//   [34048, 34064)       : dec projection + b_enc -> g_dec
#define PREP_VCONV 32768
#define PREP_SPLIT (PREP_VCONV + 1024)
#define PREP_CONV  (PREP_SPLIT + 256)
#define PREP_TOTAL (PREP_CONV + BB)

__global__ void __launch_bounds__(256) k_prep(
    const float* __restrict__ value,
    const float* __restrict__ W_enc,
    const float* __restrict__ query,
    const float* __restrict__ Wdec,
    const float* __restrict__ b_enc,
    const float* __restrict__ att_prev,
    const float* __restrict__ Wconv) {
    __shared__ float sh[256 + 2 * FWD + CCH * KW];   // conv: win|wc ; dec: q
    int bx = blockIdx.x;
    int tid = threadIdx.x;

    if (bx < PREP_VCONV) {
        size_t i = ((size_t)bx * 256 + tid) * 4;
        float4 x = *(const float4*)(value + i);
        __half2 p0 = __floats2half2_rn(x.x, x.y);
        __half2 p1 = __floats2half2_rn(x.z, x.w);
        *reinterpret_cast<uint2*>(g_Vh + i) =
            make_uint2(*(unsigned*)&p0, *(unsigned*)&p1);
    } else if (bx < PREP_SPLIT) {
        int i = (bx - PREP_VCONV) * 256 + tid;
        g_Wh[i] = __float2half_rn(W_enc[i]);
    } else if (bx < PREP_CONV) {
        int cb = bx - PREP_SPLIT;
        int t0 = (cb & 15) * 256;
        int b = cb >> 4;
        float* win = sh;                       // 256 + 200
        float* wc = sh + 256 + 2 * FWD;        // 2010
        for (int i = tid; i < 256 + 2 * FWD; i += 256) {
            int gidx = t0 - FWD + i;
            win[i] = (gidx >= 0 && gidx < TT) ? att_prev[b * TT + gidx] : 0.f;
        }
        for (int i = tid; i < CCH * KW; i += 256) wc[i] = Wconv[i];
        __syncthreads();
        float acc[CCH];
#pragma unroll
        for (int c = 0; c < CCH; ++c) acc[c] = 0.f;
        for (int h = 0; h < KW; ++h) {
            float x = win[tid + h];
#pragma unroll
            for (int c = 0; c < CCH; ++c) acc[c] += x * wc[c * KW + h];
        }
        float* o = &g_conv[(size_t)(b * TT + t0 + tid) * CCH];
#pragma unroll
        for (int c = 0; c < CCH; ++c) o[c] = acc[c];
    } else {
        int b = bx - PREP_CONV;
        float* q = sh;                         // 512
        q[tid] = query[b * DD + tid];
        q[tid + 256] = query[b * DD + tid + 256];
        __syncthreads();
#pragma unroll
        for (int rep = 0; rep < 2; ++rep) {
            int e = tid + rep * 256;
            float acc = b_enc[e];
            const float* wr = Wdec + e * DD;
#pragma unroll 8
            for (int d = 0; d < DD; ++d) acc += q[d] * wr[d];
            g_dec[b * DD + e] = acc;
        }
    }
}

// ---------------- kernel 4: fused 1-term fp16 GEMM + epilogue -----------
// 128(t) x 64(e) tile, KC=32, 3-stage cp.async (depth-2 prefetch),
// 1 barrier/iter, 256 threads (8 warps, 4m x 2n), 4 CTAs/SM (45KB smem).
#define KC 32
#define NCHUNK (DD / KC)       // 16
#define NSTAGE 3
#define ROWU 20                // padded row stride in uints (80 B)
#define ARR_A (128u * ROWU * 4u)          // 10240 B (A: 128 rows)
#define ARR_B (64u * ROWU * 4u)           // 5120 B  (B: 64 rows)
#define STAGE_BYTES (ARR_A + ARR_B)       // 15360 B
#define GEMM_SMEM (NSTAGE * STAGE_BYTES)  // 46080 B

__global__ void __launch_bounds__(256, 4)
k_gemm(const float* __restrict__ Watt,
       const float* __restrict__ wg) {
    extern __shared__ __align__(16) char dsm[];
    int tid = threadIdx.x;
    int b = blockIdx.z;
    int e0 = blockIdx.x * 64;              // N-block fastest -> A L2 reuse
    int t0 = blockIdx.y * 128;
    int lane = tid & 31, warp = tid >> 5;
    int wm = warp & 3, wn = warp >> 2;     // 4m x 2n warps, 32x32 warp tile
    int g = lane >> 2, c = lane & 3;

    float acc[2][4][4];
#pragma unroll
    for (int mt = 0; mt < 2; ++mt)
#pragma unroll
        for (int nt = 0; nt < 4; ++nt)
#pragma unroll
            for (int q = 0; q < 4; ++q) acc[mt][nt][q] = 0.f;

    unsigned sbase = (unsigned)__cvta_generic_to_shared(dsm);

    // cp.async A: row = tid>>1 (0..127), 32B per thread
    int rowA = tid >> 1, hsegA = (tid & 1) * 2;
    unsigned soffA = (unsigned)(rowA * ROWU * 4 + hsegA * 16);
    const __half* gA = g_Vh + ((size_t)(b * TT + t0 + rowA)) * DD + hsegA * 8;
    // cp.async B: row = tid>>2 (0..63), 16B per thread
    int rowB = tid >> 2, segB = tid & 3;
    unsigned soffB = (unsigned)(ARR_A + rowB * ROWU * 4 + segB * 16);
    const __half* gB = g_Wh + (size_t)(e0 + rowB) * DD + segB * 8;

#define ISSUE_STAGE(s, k0)                                                    \
    do {                                                                      \
        unsigned sb = sbase + (unsigned)(s) * STAGE_BYTES;                    \
        CP_ASYNC16(sb + soffA, gA + (k0));                                    \
        CP_ASYNC16(sb + soffA + 16, gA + (k0) + 8);                           \
        CP_ASYNC16(sb + soffB, gB + (k0));                                    \
    } while (0)

    int lr = ((lane >> 3) & 1) * 8 + (lane & 7);
    int lc = ((lane >> 4) & 1) * 4;

    ISSUE_STAGE(0, 0); CP_COMMIT();
    ISSUE_STAGE(1, KC); CP_COMMIT();

    int st = 0;                            // stage index = it % 3
    for (int it = 0; it < NCHUNK; ++it) {
        CP_WAIT(1);
        __syncthreads();
        unsigned stb = sbase + (unsigned)st * STAGE_BYTES;

#pragma unroll
        for (int ks = 0; ks < 2; ++ks) {
            unsigned kso = (unsigned)(ks * 32);    // 8 uints = 32 bytes
            unsigned af[2][4], bf[2][4];
#pragma unroll
            for (int mt = 0; mt < 2; ++mt) {
                unsigned ao = stb +
                    (unsigned)((wm * 32 + mt * 16 + lr) * ROWU * 4 + lc * 4) + kso;
                ldsm4(af[mt], ao);
            }
#pragma unroll
            for (int ntp = 0; ntp < 2; ++ntp) {
                unsigned bo = stb + ARR_A +
                    (unsigned)((wn * 32 + ntp * 16 + lr) * ROWU * 4 + lc * 4) + kso;
                ldsm4(bf[ntp], bo);
            }
            // nt-major: consecutive MMAs hit different accumulators
#pragma unroll
            for (int ntp = 0; ntp < 2; ++ntp)
#pragma unroll
                for (int sub = 0; sub < 2; ++sub)
#pragma unroll
                    for (int mt = 0; mt < 2; ++mt)
                        mma_f16(acc[mt][ntp * 2 + sub], af[mt],
                                bf[ntp][sub], bf[ntp][2 + sub]);
        }
        // reissue the stage consumed LAST iteration (protected by this
        // iteration's __syncthreads): slot (it+2)%3
        if (it + 2 < NCHUNK) {
            int ns = st + 2; if (ns >= 3) ns -= 3;
            ISSUE_STAGE(ns, (it + 2) * KC);
        }
        CP_COMMIT();
        if (++st == 3) st = 0;
    }
    __syncthreads();   // all stages consumed; safe to overlay epilogue

    // ---- epilogue smem overlay on dynamic smem ----
    float* econv = (float*)dsm;              // [128][10]
    float* ewatt = econv + 1280;             // [64][10]
    float* edec  = ewatt + 640;              // [64]
    float* ewg   = edec + 64;                // [64]
    float* ered  = ewg + 64;                 // [128][2]

    for (int i = tid; i < 1280; i += 256) {
        int row = i / 10, cc = i - row * 10;
        econv[i] = g_conv[(size_t)(b * TT + t0 + row) * CCH + cc];
    }
    for (int i = tid; i < 640; i += 256) {
        int row = i / 10, cc = i - row * 10;
        ewatt[i] = Watt[(e0 + row) * CCH + cc];
    }
    if (tid < 64) {
        edec[tid] = g_dec[b * DD + e0 + tid];
        ewg[tid] = wg[e0 + tid];
    }
    __syncthreads();

    float rowsum[2][2];
#pragma unroll
    for (int mt = 0; mt < 2; ++mt)
#pragma unroll
        for (int rr = 0; rr < 2; ++rr) {
            int rowl = wm * 32 + mt * 16 + rr * 8 + g;
            float sacc = 0.f;
#pragma unroll
            for (int nt = 0; nt < 4; ++nt)
#pragma unroll
                for (int q = 0; q < 2; ++q) {
                    int el = wn * 32 + nt * 8 + 2 * c + q;
                    float v = acc[mt][nt][rr * 2 + q] + edec[el];
#pragma unroll
                    for (int cc = 0; cc < CCH; ++cc)
                        v += econv[rowl * 10 + cc] * ewatt[el * 10 + cc];
                    sacc += ewg[el] * tanh_fast(v);
                }
            rowsum[mt][rr] = sacc;
        }
#pragma unroll
    for (int mt = 0; mt < 2; ++mt)
#pragma unroll
        for (int rr = 0; rr < 2; ++rr) {
            float v = rowsum[mt][rr];
            v += __shfl_xor_sync(0xffffffffu, v, 1);
            v += __shfl_xor_sync(0xffffffffu, v, 2);
            rowsum[mt][rr] = v;
        }
    if (c == 0) {
#pragma unroll
        for (int mt = 0; mt < 2; ++mt)
#pragma unroll
            for (int rr = 0; rr < 2; ++rr)
                ered[(wm * 32 + mt * 16 + rr * 8 + g) * 2 + wn] = rowsum[mt][rr];
    }
    __syncthreads();
    if (tid < 128) {
        float val = ered[tid * 2] + ered[tid * 2 + 1];
        g_epart[((size_t)blockIdx.x * BB + b) * TT + t0 + tid] = val;
    }
}

// ---------------- kernel 5: masked sharpened softmax ----------------
__global__ void k_softmax(const int* __restrict__ lens,
                          float* __restrict__ out_att) {
    int b = blockIdx.x;
    int tid = threadIdx.x;            // 256
    int len = lens[b];
    __shared__ float sred[256];
    float ev[16];
    float lmax = -INFINITY;
#pragma unroll
    for (int i = 0; i < 16; ++i) {
        int t = tid + i * 256;
        float e = 0.f;
#pragma unroll
        for (int p = 0; p < NBLK; ++p)
            e += g_epart[(p * BB + b) * TT + t];
        e *= 2.0f;                    // sharpening
        ev[i] = (t < len) ? e : -INFINITY;
        lmax = fmaxf(lmax, ev[i]);
    }
    sred[tid] = lmax;
    __syncthreads();
    for (int s = 128; s > 0; s >>= 1) {
        if (tid < s) sred[tid] = fmaxf(sred[tid], sred[tid + s]);
        __syncthreads();
    }
    float m = sred[0];
    __syncthreads();
    float lsum = 0.f;
#pragma unroll
    for (int i = 0; i < 16; ++i) {
        float p = expf(ev[i] - m);
        ev[i] = p;
        lsum += p;
    }
    sred[tid] = lsum;
    __syncthreads();
    for (int s = 128; s > 0; s >>= 1) {
        if (tid < s) sred[tid] += sred[tid + s];
        __syncthreads();
    }
    float inv = 1.f / sred[0];
#pragma unroll
    for (int i = 0; i < 16; ++i)
        out_att[b * TT + tid + i * 256] = ev[i] * inv;
}

// ---------------- kernel 6/7: context = value^T @ weights ----------------
// reads fp16 g_Vh (halves traffic); error ~1e-4 added, still well under gate
__global__ void __launch_bounds__(128) k_ctx_part(const float* __restrict__ att) {
    int tch = blockIdx.x, b = blockIdx.y;
    int d4 = threadIdx.x * 4;
    const __half* vb = g_Vh + (size_t)b * TT * DD;
    const float* ab = att + b * TT;
    float a0 = 0.f, a1 = 0.f, a2 = 0.f, a3 = 0.f;
    int tbase = tch * (TT / TCH);
#pragma unroll 4
    for (int t = tbase; t < tbase + TT / TCH; ++t) {
        uint2 raw = *(const uint2*)(vb + (size_t)t * DD + d4);
        __half2 h01 = *reinterpret_cast<__half2*>(&raw.x);
        __half2 h23 = *reinterpret_cast<__half2*>(&raw.y);
        float2 f01 = __half22float2(h01);
        float2 f23 = __half22float2(h23);
        float w = __ldg(ab + t);
        a0 += f01.x * w; a1 += f01.y * w; a2 += f23.x * w; a3 += f23.y * w;
    }
    float* o = &g_ctxpart[((size_t)tch * BB + b) * DD + d4];
    o[0] = a0; o[1] = a1; o[2] = a2; o[3] = a3;
}

__global__ void k_ctx_final(float* __restrict__ out) {
    int idx = blockIdx.x * 256 + threadIdx.x;
    float v = 0.f;
#pragma unroll
    for (int p = 0; p < TCH; ++p) v += g_ctxpart[p * BB * DD + idx];
    out[idx] = v;
}

// ---------------- launch ----------------
extern "C" void kernel_launch(void* const* d_in, const int* in_sizes, int n_in,
                              void* d_out, int out_size) {
    const float* value    = (const float*)d_in[0];
    const float* query    = (const float*)d_in[1];
    const int*   lens     = (const int*)d_in[2];
    const float* att_prev = (const float*)d_in[3];
    const float* W_enc    = (const float*)d_in[4];
    const float* b_enc    = (const float*)d_in[5];
    const float* W_dec    = (const float*)d_in[6];
    const float* W_att    = (const float*)d_in[7];
    const float* W_conv   = (const float*)d_in[8];
    const float* w_g      = (const float*)d_in[9];
    // d_in[10] = b_g: uniform logit shift, cancels in softmax.

    float* out = (float*)d_out;
    float* out_att = out + BB * DD;

    cudaFuncSetAttribute(k_gemm, cudaFuncAttributeMaxDynamicSharedMemorySize,
                         GEMM_SMEM);

    k_prep<<<PREP_TOTAL, 256>>>(value, W_enc, query, W_dec, b_enc,
                                att_prev, W_conv);
    k_gemm<<<dim3(NBLK, TT / 128, BB), 256, GEMM_SMEM>>>(W_att, w_g);
    k_softmax<<<BB, 256>>>(lens, out_att);
    k_ctx_part<<<dim3(TCH, BB), 128>>>(out_att);
    k_ctx_final<<<BB * DD / 256, 256>>>(out);
}

// round 17
// speedup vs baseline: 1.9243x; 1.0177x over previous
#include <cuda_runtime.h>
#include <cuda_fp16.h>
#include <math.h>

#define BB 16
#define TT 4096
#define DD 512
#define CCH 10
#define FWD 100
#define KW 201          // 2*FW+1
#define NBLK 8          // N split: 8 tiles of 64 columns
#define TCH 128         // context T-chunks (32 t's each)

// ---------------- device scratch (static, allowed) ----------------
__device__ __align__(16) __half g_Wh[DD * DD];                  // W_enc fp16
__device__ __align__(16) __half g_Vh[(size_t)BB * TT * DD];     // value fp16
__device__ float g_dec[BB * DD];                 // dec projection + b_enc
__device__ float g_conv[BB * TT * CCH];          // conv features [b][t][c]
__device__ float g_epart[NBLK * BB * TT];        // partial logits per N-block
__device__ float g_ctxpart[TCH * BB * DD];       // context partials per T-chunk

// ---------------- helpers ----------------
__device__ __forceinline__ float tanh_fast(float x) {
    float ax = fabsf(x);
    float z = __expf(-2.0f * ax);
    float t = __fdividef(1.0f - z, 1.0f + z);
    return copysignf(t, x);
}

// fp16 MMA, fp32 accum. NOT volatile: ptxas may interleave freely.
__device__ __forceinline__ void mma_f16(float* d, const unsigned* a,
                                        unsigned b0, unsigned b1) {
    asm("mma.sync.aligned.m16n8k16.row.col.f32.f16.f16.f32 "
        "{%0,%1,%2,%3}, {%4,%5,%6,%7}, {%8,%9}, {%0,%1,%2,%3};\n"
        : "+f"(d[0]), "+f"(d[1]), "+f"(d[2]), "+f"(d[3])
        : "r"(a[0]), "r"(a[1]), "r"(a[2]), "r"(a[3]), "r"(b0), "r"(b1));
}

__device__ __forceinline__ void ldsm4(unsigned* r, unsigned addr) {
    asm volatile("ldmatrix.sync.aligned.m8n8.x4.shared.b16 {%0,%1,%2,%3}, [%4];\n"
                 : "=r"(r[0]), "=r"(r[1]), "=r"(r[2]), "=r"(r[3]) : "r"(addr));
}

#define CP_ASYNC16(sm, gm) \
    asm volatile("cp.async.cg.shared.global [%0], [%1], 16;\n" :: "r"(sm), "l"(gm))
#define CP_COMMIT() asm volatile("cp.async.commit_group;\n")
#define CP_WAIT(n)  asm volatile("cp.async.wait_group %0;\n" :: "n"(n))

// ---------------- kernel 1: merged prologue ----------------
// role by blockIdx.x:
//   [0, 32768)           : value -> fp16  (DRAM-bound stream)
//   [32768, 33792)       : W_enc -> fp16
//   [33792, 34048)       : location conv -> g_conv
//   [34048, 34064)       : dec projection + b_enc -> g_dec
#define PREP_VCONV 32768
#define PREP_SPLIT (PREP_VCONV + 1024)
#define PREP_CONV  (PREP_SPLIT + 256)
#define PREP_TOTAL (PREP_CONV + BB)

__global__ void __launch_bounds__(256) k_prep(
    const float* __restrict__ value,
    const float* __restrict__ W_enc,
    const float* __restrict__ query,
    const float* __restrict__ Wdec,
    const float* __restrict__ b_enc,
    const float* __restrict__ att_prev,
    const float* __restrict__ Wconv) {
    __shared__ float sh[256 + 2 * FWD + CCH * KW];   // conv: win|wc ; dec: q
    int bx = blockIdx.x;
    int tid = threadIdx.x;

    if (bx < PREP_VCONV) {
        size_t i = ((size_t)bx * 256 + tid) * 4;
        float4 x = *(const float4*)(value + i);
        __half2 p0 = __floats2half2_rn(x.x, x.y);
        __half2 p1 = __floats2half2_rn(x.z, x.w);
        *reinterpret_cast<uint2*>(g_Vh + i) =
            make_uint2(*(unsigned*)&p0, *(unsigned*)&p1);
    } else if (bx < PREP_SPLIT) {
        int i = (bx - PREP_VCONV) * 256 + tid;
        g_Wh[i] = __float2half_rn(W_enc[i]);
    } else if (bx < PREP_CONV) {
        int cb = bx - PREP_SPLIT;
        int t0 = (cb & 15) * 256;
        int b = cb >> 4;
        float* win = sh;                       // 256 + 200
        float* wc = sh + 256 + 2 * FWD;        // 2010
        for (int i = tid; i < 256 + 2 * FWD; i += 256) {
            int gidx = t0 - FWD + i;
            win[i] = (gidx >= 0 && gidx < TT) ? att_prev[b * TT + gidx] : 0.f;
        }
        for (int i = tid; i < CCH * KW; i += 256) wc[i] = Wconv[i];
        __syncthreads();
        float acc[CCH];
#pragma unroll
        for (int c = 0; c < CCH; ++c) acc[c] = 0.f;
        for (int h = 0; h < KW; ++h) {
            float x = win[tid + h];
#pragma unroll
            for (int c = 0; c < CCH; ++c) acc[c] += x * wc[c * KW + h];
        }
        float* o = &g_conv[(size_t)(b * TT + t0 + tid) * CCH];
#pragma unroll
        for (int c = 0; c < CCH; ++c) o[c] = acc[c];
    } else {
        int b = bx - PREP_CONV;
        float* q = sh;                         // 512
        q[tid] = query[b * DD + tid];
        q[tid + 256] = query[b * DD + tid + 256];
        __syncthreads();
#pragma unroll
        for (int rep = 0; rep < 2; ++rep) {
            int e = tid + rep * 256;
            float acc = b_enc[e];
            const float* wr = Wdec + e * DD;
#pragma unroll 8
            for (int d = 0; d < DD; ++d) acc += q[d] * wr[d];
            g_dec[b * DD + e] = acc;
        }
    }
}

// ---------------- kernel 4: fused 1-term fp16 GEMM + epilogue -----------
// 128(t) x 64(e) tile, KC=32, 3-stage cp.async (depth-2 prefetch),
// 1 barrier/iter, 256 threads (8 warps, 4m x 2n), 4 CTAs/SM (45KB smem).
#define KC 32
#define NCHUNK (DD / KC)       // 16
#define NSTAGE 3
#define ROWU 20                // padded row stride in uints (80 B)
#define ARR_A (128u * ROWU * 4u)          // 10240 B (A: 128 rows)
#define ARR_B (64u * ROWU * 4u)           // 5120 B  (B: 64 rows)
#define STAGE_BYTES (ARR_A + ARR_B)       // 15360 B
#define GEMM_SMEM (NSTAGE * STAGE_BYTES)  // 46080 B

__global__ void __launch_bounds__(256, 4)
k_gemm(const float* __restrict__ Watt,
       const float* __restrict__ wg) {
    extern __shared__ __align__(16) char dsm[];
    int tid = threadIdx.x;
    int b = blockIdx.z;
    int e0 = blockIdx.x * 64;              // N-block fastest -> A L2 reuse
    int t0 = blockIdx.y * 128;
    int lane = tid & 31, warp = tid >> 5;
    int wm = warp & 3, wn = warp >> 2;     // 4m x 2n warps, 32x32 warp tile
    int g = lane >> 2, c = lane & 3;

    float acc[2][4][4];
#pragma unroll
    for (int mt = 0; mt < 2; ++mt)
#pragma unroll
        for (int nt = 0; nt < 4; ++nt)
#pragma unroll
            for (int q = 0; q < 4; ++q) acc[mt][nt][q] = 0.f;

    unsigned sbase = (unsigned)__cvta_generic_to_shared(dsm);

    // cp.async A: row = tid>>1 (0..127), 32B per thread
    int rowA = tid >> 1, hsegA = (tid & 1) * 2;
    unsigned soffA = (unsigned)(rowA * ROWU * 4 + hsegA * 16);
    const __half* gA = g_Vh + ((size_t)(b * TT + t0 + rowA)) * DD + hsegA * 8;
    // cp.async B: row = tid>>2 (0..63), 16B per thread
    int rowB = tid >> 2, segB = tid & 3;
    unsigned soffB = (unsigned)(ARR_A + rowB * ROWU * 4 + segB * 16);
    const __half* gB = g_Wh + (size_t)(e0 + rowB) * DD + segB * 8;

#define ISSUE_STAGE(s, k0)                                                    \
    do {                                                                      \
        unsigned sb = sbase + (unsigned)(s) * STAGE_BYTES;                    \
        CP_ASYNC16(sb + soffA, gA + (k0));                                    \
        CP_ASYNC16(sb + soffA + 16, gA + (k0) + 8);                           \
        CP_ASYNC16(sb + soffB, gB + (k0));                                    \
    } while (0)

    int lr = ((lane >> 3) & 1) * 8 + (lane & 7);
    int lc = ((lane >> 4) & 1) * 4;

    ISSUE_STAGE(0, 0); CP_COMMIT();
    ISSUE_STAGE(1, KC); CP_COMMIT();

    int st = 0;                            // stage index = it % 3
    for (int it = 0; it < NCHUNK; ++it) {
        CP_WAIT(1);
        __syncthreads();
        unsigned stb = sbase + (unsigned)st * STAGE_BYTES;

#pragma unroll
        for (int ks = 0; ks < 2; ++ks) {
            unsigned kso = (unsigned)(ks * 32);    // 8 uints = 32 bytes
            unsigned af[2][4], bf[2][4];
#pragma unroll
            for (int mt = 0; mt < 2; ++mt) {
                unsigned ao = stb +
                    (unsigned)((wm * 32 + mt * 16 + lr) * ROWU * 4 + lc * 4) + kso;
                ldsm4(af[mt], ao);
            }
#pragma unroll
            for (int ntp = 0; ntp < 2; ++ntp) {
                unsigned bo = stb + ARR_A +
                    (unsigned)((wn * 32 + ntp * 16 + lr) * ROWU * 4 + lc * 4) + kso;
                ldsm4(bf[ntp], bo);
            }
            // nt-major: consecutive MMAs hit different accumulators
#pragma unroll
            for (int ntp = 0; ntp < 2; ++ntp)
#pragma unroll
                for (int sub = 0; sub < 2; ++sub)
#pragma unroll
                    for (int mt = 0; mt < 2; ++mt)
                        mma_f16(acc[mt][ntp * 2 + sub], af[mt],
                                bf[ntp][sub], bf[ntp][2 + sub]);
        }
        // reissue the stage consumed LAST iteration (protected by this
        // iteration's __syncthreads): slot (it+2)%3
        if (it + 2 < NCHUNK) {
            int ns = st + 2; if (ns >= 3) ns -= 3;
            ISSUE_STAGE(ns, (it + 2) * KC);
        }
        CP_COMMIT();
        if (++st == 3) st = 0;
    }
    __syncthreads();   // all stages consumed; safe to overlay epilogue

    // ---- epilogue smem overlay on dynamic smem ----
    float* econv = (float*)dsm;              // [128][10]
    float* ewatt = econv + 1280;             // [64][10]
    float* edec  = ewatt + 640;              // [64]
    float* ewg   = edec + 64;                // [64]
    float* ered  = ewg + 64;                 // [128][2]

    for (int i = tid; i < 1280; i += 256) {
        int row = i / 10, cc = i - row * 10;
        econv[i] = g_conv[(size_t)(b * TT + t0 + row) * CCH + cc];
    }
    for (int i = tid; i < 640; i += 256) {
        int row = i / 10, cc = i - row * 10;
        ewatt[i] = Watt[(e0 + row) * CCH + cc];
    }
    if (tid < 64) {
        edec[tid] = g_dec[b * DD + e0 + tid];
        ewg[tid] = wg[e0 + tid];
    }
    __syncthreads();

    float rowsum[2][2];
#pragma unroll
    for (int mt = 0; mt < 2; ++mt)
#pragma unroll
        for (int rr = 0; rr < 2; ++rr) {
            int rowl = wm * 32 + mt * 16 + rr * 8 + g;
            float sacc = 0.f;
#pragma unroll
            for (int nt = 0; nt < 4; ++nt)
#pragma unroll
                for (int q = 0; q < 2; ++q) {
                    int el = wn * 32 + nt * 8 + 2 * c + q;
                    float v = acc[mt][nt][rr * 2 + q] + edec[el];
#pragma unroll
                    for (int cc = 0; cc < CCH; ++cc)
                        v += econv[rowl * 10 + cc] * ewatt[el * 10 + cc];
                    sacc += ewg[el] * tanh_fast(v);
                }
            rowsum[mt][rr] = sacc;
        }
#pragma unroll
    for (int mt = 0; mt < 2; ++mt)
#pragma unroll
        for (int rr = 0; rr < 2; ++rr) {
            float v = rowsum[mt][rr];
            v += __shfl_xor_sync(0xffffffffu, v, 1);
            v += __shfl_xor_sync(0xffffffffu, v, 2);
            rowsum[mt][rr] = v;
        }
    if (c == 0) {
#pragma unroll
        for (int mt = 0; mt < 2; ++mt)
#pragma unroll
            for (int rr = 0; rr < 2; ++rr)
                ered[(wm * 32 + mt * 16 + rr * 8 + g) * 2 + wn] = rowsum[mt][rr];
    }
    __syncthreads();
    if (tid < 128) {
        float val = ered[tid * 2] + ered[tid * 2 + 1];
        g_epart[((size_t)blockIdx.x * BB + b) * TT + t0 + tid] = val;
    }
}

// ---------------- kernel 5: masked sharpened softmax ----------------
__global__ void k_softmax(const int* __restrict__ lens,
                          float* __restrict__ out_att) {
    int b = blockIdx.x;
    int tid = threadIdx.x;            // 256
    int len = lens[b];
    __shared__ float sred[256];
    float ev[16];
    float lmax = -INFINITY;
#pragma unroll
    for (int i = 0; i < 16; ++i) {
        int t = tid + i * 256;
        float e = 0.f;
#pragma unroll
        for (int p = 0; p < NBLK; ++p)
            e += g_epart[(p * BB + b) * TT + t];
        e *= 2.0f;                    // sharpening
        ev[i] = (t < len) ? e : -INFINITY;
        lmax = fmaxf(lmax, ev[i]);
    }
    sred[tid] = lmax;
    __syncthreads();
    for (int s = 128; s > 0; s >>= 1) {
        if (tid < s) sred[tid] = fmaxf(sred[tid], sred[tid + s]);
        __syncthreads();
    }
    float m = sred[0];
    __syncthreads();
    float lsum = 0.f;
#pragma unroll
    for (int i = 0; i < 16; ++i) {
        float p = expf(ev[i] - m);
        ev[i] = p;
        lsum += p;
    }
    sred[tid] = lsum;
    __syncthreads();
    for (int s = 128; s > 0; s >>= 1) {
        if (tid < s) sred[tid] += sred[tid + s];
        __syncthreads();
    }
    float inv = 1.f / sred[0];
#pragma unroll
    for (int i = 0; i < 16; ++i)
        out_att[b * TT + tid + i * 256] = ev[i] * inv;
}

// ---------------- kernel 6/7: context = value^T @ weights ----------------
// reads fp16 g_Vh; TCH=128 chunks of 32 t's -> 2048 CTAs (occ ~85%)
__global__ void __launch_bounds__(128) k_ctx_part(const float* __restrict__ att) {
    int tch = blockIdx.x, b = blockIdx.y;
    int d4 = threadIdx.x * 4;
    const __half* vb = g_Vh + (size_t)b * TT * DD;
    const float* ab = att + b * TT;
    float a0 = 0.f, a1 = 0.f, a2 = 0.f, a3 = 0.f;
    int tbase = tch * (TT / TCH);
#pragma unroll 8
    for (int t = tbase; t < tbase + TT / TCH; ++t) {
        uint2 raw = *(const uint2*)(vb + (size_t)t * DD + d4);
        __half2 h01 = *reinterpret_cast<__half2*>(&raw.x);
        __half2 h23 = *reinterpret_cast<__half2*>(&raw.y);
        float2 f01 = __half22float2(h01);
        float2 f23 = __half22float2(h23);
        float w = __ldg(ab + t);
        a0 += f01.x * w; a1 += f01.y * w; a2 += f23.x * w; a3 += f23.y * w;
    }
    float* o = &g_ctxpart[((size_t)tch * BB + b) * DD + d4];
    o[0] = a0; o[1] = a1; o[2] = a2; o[3] = a3;
}

__global__ void k_ctx_final(float* __restrict__ out) {
    int idx = blockIdx.x * 256 + threadIdx.x;
    float v = 0.f;
#pragma unroll
    for (int p = 0; p < TCH; ++p) v += g_ctxpart[p * BB * DD + idx];
    out[idx] = v;
}

// ---------------- launch ----------------
extern "C" void kernel_launch(void* const* d_in, const int* in_sizes, int n_in,
                              void* d_out, int out_size) {
    const float* value    = (const float*)d_in[0];
    const float* query    = (const float*)d_in[1];
    const int*   lens     = (const int*)d_in[2];
    const float* att_prev = (const float*)d_in[3];
    const float* W_enc    = (const float*)d_in[4];
    const float* b_enc    = (const float*)d_in[5];
    const float* W_dec    = (const float*)d_in[6];
    const float* W_att    = (const float*)d_in[7];
    const float* W_conv   = (const float*)d_in[8];
    const float* w_g      = (const float*)d_in[9];
    // d_in[10] = b_g: uniform logit shift, cancels in softmax.

    float* out = (float*)d_out;
    float* out_att = out + BB * DD;

    cudaFuncSetAttribute(k_gemm, cudaFuncAttributeMaxDynamicSharedMemorySize,
                         GEMM_SMEM);

    k_prep<<<PREP_TOTAL, 256>>>(value, W_enc, query, W_dec, b_enc,
                                att_prev, W_conv);
    k_gemm<<<dim3(NBLK, TT / 128, BB), 256, GEMM_SMEM>>>(W_att, w_g);
    k_softmax<<<BB, 256>>>(lens, out_att);
    k_ctx_part<<<dim3(TCH, BB), 128>>>(out_att);
    k_ctx_final<<<BB * DD / 256, 256>>>(out);
}